// round 12
// baseline (speedup 1.0000x reference)
#include <cuda_runtime.h>
#include <cuda_fp16.h>
#include <cstdint>

#define BATCH   32
#define SEQ     577
#define EMBED   768
#define HEADS   12
#define HDIM    64
#define MROWS   (BATCH * SEQ)        // 18464
#define QKV_N   (3 * EMBED)          // 2304
// log2 domain: Q pre-scaled by ATT_SCALE * log2(e); softmax uses ex2.approx
#define ATT_SCALE_LOG2E 0.1803368801111204f

// ---------------- scratch (module-load allocated, no runtime allocs) -------
__device__ __half g_Qh[(size_t)BATCH * HEADS * SEQ * HDIM];   // [b,h,n,d], pre-scaled
__device__ __half g_Kh[(size_t)BATCH * HEADS * SEQ * HDIM];
__device__ __half g_Vh[(size_t)BATCH * HEADS * SEQ * HDIM];
__device__ __half g_Oh[(size_t)MROWS * EMBED];                // attention out (half)
__device__ __half g_Xh[(size_t)MROWS * EMBED];                // half X
__device__ __half g_Wqkvh[(size_t)EMBED * QKV_N];             // half W_qkv (row-major)
__device__ __half g_Wprojh[(size_t)EMBED * EMBED];            // half W_proj (row-major)

// ---------------- PTX helpers ----------------------------------------------
__device__ __forceinline__ uint32_t smem_u32(const void* p) {
    uint32_t a;
    asm("{ .reg .u64 t; cvta.to.shared.u64 t, %1; cvt.u32.u64 %0, t; }"
        : "=r"(a) : "l"(p));
    return a;
}
__device__ __forceinline__ void cp16(uint32_t dst, const void* src, bool pred) {
    int sz = pred ? 16 : 0;
    asm volatile("cp.async.cg.shared.global [%0], [%1], 16, %2;\n"
                 :: "r"(dst), "l"(src), "r"(sz));
}
#define CP_COMMIT() asm volatile("cp.async.commit_group;\n" ::: "memory")
#define CP_WAIT1()  asm volatile("cp.async.wait_group 1;\n" ::: "memory")
#define CP_WAIT0()  asm volatile("cp.async.wait_group 0;\n" ::: "memory")

__device__ __forceinline__ void ldsm_x4(uint32_t (&r)[4], uint32_t addr) {
    asm volatile("ldmatrix.sync.aligned.m8n8.x4.shared.b16 {%0,%1,%2,%3}, [%4];"
                 : "=r"(r[0]), "=r"(r[1]), "=r"(r[2]), "=r"(r[3]) : "r"(addr));
}
__device__ __forceinline__ void ldsm_x4t(uint32_t (&r)[4], uint32_t addr) {
    asm volatile("ldmatrix.sync.aligned.m8n8.x4.trans.shared.b16 {%0,%1,%2,%3}, [%4];"
                 : "=r"(r[0]), "=r"(r[1]), "=r"(r[2]), "=r"(r[3]) : "r"(addr));
}
__device__ __forceinline__ void mma16816(float (&d)[4], const uint32_t (&a)[4],
                                         uint32_t b0, uint32_t b1) {
    asm volatile("mma.sync.aligned.m16n8k16.row.col.f32.f16.f16.f32 "
                 "{%0,%1,%2,%3}, {%4,%5,%6,%7}, {%8,%9}, {%0,%1,%2,%3};"
                 : "+f"(d[0]), "+f"(d[1]), "+f"(d[2]), "+f"(d[3])
                 : "r"(a[0]), "r"(a[1]), "r"(a[2]), "r"(a[3]), "r"(b0), "r"(b1));
}
__device__ __forceinline__ float ex2(float x) {
    float r;
    asm("ex2.approx.ftz.f32 %0, %1;" : "=f"(r) : "f"(x));
    return r;
}

// ---------------- GEMM tiling (raw mma, fp16) -------------------------------
// BM=128, BN=256, BK=64; 8 warps as 2(m) x 4(n); warp tile 64x64.
// 0.25 ldsm per MMA (vs 0.375 at 64x32) — cuts the binding smem traffic 33%.
// 3-stage pipeline, wait_group 1 + one __syncthreads per K-iteration.
// A: padded rows (72 halves) — conflict-free ldsm.
// B: 64 rows x 32 chunks(16B), chunk swizzle c^(r&7) — conflict-free x4t.
#define BM 128
#define BN 256
#define BK 64
#define LDA 72
#define A_ST (BM * LDA)              // 9216 halves (18432 B)
#define B_ST_B 32768                 // 64 * 512 B
#define KTILES (EMBED / BK)          // 12
#define GEMM_SMEM_BYTES (3 * (A_ST * 2 + B_ST_B))   // 153600

template <typename EPI>
__device__ __forceinline__ void gemm_mma(
    const __half* __restrict__ Ag, const __half* __restrict__ Bg, int ldb_g,
    int m0, int n0, bool mtail, EPI epi)
{
    extern __shared__ __half smh[];
    uint32_t sA_u = smem_u32(smh);
    uint32_t sB_u = sA_u + 3 * A_ST * 2;

    const int tid  = threadIdx.x;
    const int warp = tid >> 5;
    const int lane = tid & 31;
    const int wm   = warp >> 2;      // 0..1
    const int wn   = warp & 3;       // 0..3

    auto issue = [&](int kt, int st) {
        const int k0 = kt * BK;
        // A: 128 rows x 8 chunks -> 4/thread
        #pragma unroll
        for (int j = 0; j < 4; j++) {
            int i  = tid + j * 256;
            int r  = i >> 3;
            int ch = i & 7;
            int gm = m0 + r;
            bool p = !mtail || (gm < MROWS);
            cp16(sA_u + (uint32_t)(st * A_ST + r * LDA + ch * 8) * 2,
                 Ag + (size_t)gm * EMBED + k0 + ch * 8, p);
        }
        // B: 64 rows x 32 chunks -> 8/thread, swizzled
        #pragma unroll
        for (int j = 0; j < 8; j++) {
            int i  = tid + j * 256;
            int r  = i >> 5;
            int c  = i & 31;
            cp16(sB_u + (uint32_t)(st * B_ST_B + r * 512 + ((c ^ (r & 7)) << 4)),
                 Bg + (size_t)(k0 + r) * ldb_g + n0 + c * 8, true);
        }
        CP_COMMIT();
    };

    float acc[4][8][4];
    #pragma unroll
    for (int i = 0; i < 4; i++)
        #pragma unroll
        for (int j = 0; j < 8; j++)
            #pragma unroll
            for (int c = 0; c < 4; c++) acc[i][j][c] = 0.f;

    issue(0, 0);
    issue(1, 1);

    const int l16 = lane & 15;
    const int lh  = lane >> 4;       // 0..1

    for (int it = 0; it < KTILES; it++) {
        if (it == KTILES - 1) CP_WAIT0(); else CP_WAIT1();
        __syncthreads();
        if (it + 2 < KTILES) issue(it + 2, (it + 2) % 3);

        const int st = it % 3;
        const uint32_t aBase = sA_u + (uint32_t)(st * A_ST) * 2;
        const uint32_t bBase = sB_u + (uint32_t)(st * B_ST_B);

        #pragma unroll
        for (int kk = 0; kk < 4; kk++) {
            uint32_t am[4][4];
            #pragma unroll
            for (int i = 0; i < 4; i++) {
                int row = wm * 64 + i * 16 + l16;
                ldsm_x4(am[i], aBase + (uint32_t)(row * LDA + kk * 16 + lh * 8) * 2);
            }
            uint32_t bf[4][4];
            #pragma unroll
            for (int jj = 0; jj < 4; jj++) {
                int r = kk * 16 + l16;
                int c = wn * 8 + jj * 2 + lh;
                ldsm_x4t(bf[jj], bBase + (uint32_t)(r * 512 + ((c ^ (r & 7)) << 4)));
            }
            #pragma unroll
            for (int i = 0; i < 4; i++) {
                #pragma unroll
                for (int jj = 0; jj < 4; jj++) {
                    mma16816(acc[i][jj * 2 + 0], am[i], bf[jj][0], bf[jj][1]);
                    mma16816(acc[i][jj * 2 + 1], am[i], bf[jj][2], bf[jj][3]);
                }
            }
        }
    }

    // direct register epilogue (warp covers n-range wn*64 .. wn*64+63)
    const int row0 = m0 + wm * 64 + (lane >> 2);
    const int gnb  = n0 + wn * 64 + 2 * (lane & 3);
    #pragma unroll
    for (int i = 0; i < 4; i++) {
        #pragma unroll
        for (int j = 0; j < 8; j++) {
            int gn = gnb + j * 8;
            epi(row0 + i * 16,     gn, acc[i][j][0], acc[i][j][1]);
            epi(row0 + i * 16 + 8, gn, acc[i][j][2], acc[i][j][3]);
        }
    }
}

// ===========================================================================
// Kernel 1: QKV GEMM + scatter epilogue (Q scaled by ATT_SCALE*log2e)
// ===========================================================================
__global__ void __launch_bounds__(256, 1) gemm_qkv_kernel(const __half* __restrict__ X,
                                                          const __half* __restrict__ W)
{
    const int m0 = blockIdx.y * BM;
    const int n0 = blockIdx.x * BN;
    const bool mtail = (m0 + BM > MROWS);

    gemm_mma(X, W, QKV_N, m0, n0, mtail,
        [&](int gm, int gn, float v0, float v1) {
            if (gm >= MROWS) return;
            int b   = gm / SEQ;
            int tok = gm - b * SEQ;
            int s   = gn / EMBED;
            int rem = gn - s * EMBED;
            int h   = rem >> 6;
            int d   = rem & 63;
            size_t idx = ((size_t)(b * HEADS + h) * SEQ + tok) * HDIM + d;
            if (s == 0) {
                *(__half2*)(g_Qh + idx) =
                    __floats2half2_rn(v0 * ATT_SCALE_LOG2E, v1 * ATT_SCALE_LOG2E);
            } else if (s == 1) {
                *(__half2*)(g_Kh + idx) = __floats2half2_rn(v0, v1);
            } else {
                *(__half2*)(g_Vh + idx) = __floats2half2_rn(v0, v1);
            }
        });
}

// ===========================================================================
// Kernel 3: projection GEMM.  out = g_Oh @ Wp + bias
// ===========================================================================
__global__ void __launch_bounds__(256, 1) gemm_proj_kernel(const __half* __restrict__ A,
                                                           const __half* __restrict__ W,
                                                           const float* __restrict__ bias,
                                                           float* __restrict__ out)
{
    const int m0 = blockIdx.y * BM;
    const int n0 = blockIdx.x * BN;
    const bool mtail = (m0 + BM > MROWS);

    gemm_mma(A, W, EMBED, m0, n0, mtail,
        [&](int gm, int gn, float v0, float v1) {
            if (gm >= MROWS) return;
            float2 v;
            v.x = v0 + bias[gn];
            v.y = v1 + bias[gn + 1];
            *(float2*)(out + (size_t)gm * EMBED + gn) = v;
        });
}

// ===========================================================================
// Kernel 2: flash attention, FA2-style (unchanged from R11)
// ===========================================================================
#define KV_TILES ((SEQ + 63) / 64)                 // 10
#define LDH 72
#define KV_TILE_H (64 * LDH)
#define Q_TILE_H  (128 * LDH)
#define ATTN_SMEM ((Q_TILE_H + 4 * KV_TILE_H) * 2) // 55296 B

__global__ void __launch_bounds__(256) attn_kernel()
{
    extern __shared__ __half smh[];
    const int tid  = threadIdx.x;
    const int warp = tid >> 5;
    const int lane = tid & 31;
    const int bh   = blockIdx.y;
    const int b    = bh / HEADS;
    const int h    = bh - b * HEADS;
    const int q0   = blockIdx.x * 128;

    const __half* Qg = g_Qh + (size_t)bh * SEQ * HDIM;
    const __half* Kg = g_Kh + (size_t)bh * SEQ * HDIM;
    const __half* Vg = g_Vh + (size_t)bh * SEQ * HDIM;

    uint32_t Qs_u = smem_u32(smh);
    uint32_t Ks_u = Qs_u + Q_TILE_H * 2;
    uint32_t Vs_u = Ks_u + 2 * KV_TILE_H * 2;

    auto issue_kv = [&](int kt, int st) {
        const int kbase = kt * 64;
        #pragma unroll
        for (int j = 0; j < 2; j++) {
            int i  = tid + j * 256;
            int r  = i >> 3;
            int c8 = (i & 7) << 3;
            int ki = kbase + r;
            bool p = ki < SEQ;
            uint32_t off = (uint32_t)(st * KV_TILE_H + r * LDH + c8) * 2;
            cp16(Ks_u + off, Kg + (size_t)ki * HDIM + c8, p);
            cp16(Vs_u + off, Vg + (size_t)ki * HDIM + c8, p);
        }
        CP_COMMIT();
    };

    #pragma unroll
    for (int j = 0; j < 4; j++) {
        int i  = tid + j * 256;
        int r  = i >> 3;
        int c8 = (i & 7) << 3;
        int qi = q0 + r;
        cp16(Qs_u + (uint32_t)(r * LDH + c8) * 2, Qg + (size_t)qi * HDIM + c8, qi < SEQ);
    }
    issue_kv(0, 0);

    CP_WAIT0();
    __syncthreads();

    uint32_t qa[4][4];
    {
        const int l8  = lane & 7;
        const int sel = lane >> 3;
        #pragma unroll
        for (int kk = 0; kk < 4; kk++) {
            uint32_t addr = Qs_u +
                (uint32_t)((warp * 16 + (sel & 1) * 8 + l8) * LDH + kk * 16 + (sel >> 1) * 8) * 2;
            ldsm_x4(qa[kk], addr);
        }
    }
    if (KV_TILES > 1) issue_kv(1, 1);

    float o[8][4];
    #pragma unroll
    for (int j = 0; j < 8; j++)
        #pragma unroll
        for (int c = 0; c < 4; c++) o[j][c] = 0.f;
    float mrow[2] = {-1e30f, -1e30f};
    float lrow[2] = {0.f, 0.f};

    const int l8  = lane & 7;
    const int grp = lane >> 3;       // 0..3

    for (int kt = 0; kt < KV_TILES; kt++) {
        const int st = kt & 1;
        if (kt > 0) {
            CP_WAIT0();
            __syncthreads();
            if (kt + 1 < KV_TILES) issue_kv(kt + 1, st ^ 1);
        }
        const uint32_t Kt_u = Ks_u + (uint32_t)(st * KV_TILE_H) * 2;
        const uint32_t Vt_u = Vs_u + (uint32_t)(st * KV_TILE_H) * 2;

        float s[8][4];
        #pragma unroll
        for (int j = 0; j < 8; j++)
            #pragma unroll
            for (int c = 0; c < 4; c++) s[j][c] = 0.f;

        #pragma unroll
        for (int kk = 0; kk < 4; kk++) {
            #pragma unroll
            for (int jp = 0; jp < 4; jp++) {
                uint32_t bk[4];
                uint32_t addr = Kt_u +
                    (uint32_t)(((jp * 2 + (grp >> 1)) * 8 + l8) * LDH
                               + kk * 16 + (grp & 1) * 8) * 2;
                ldsm_x4(bk, addr);
                mma16816(s[jp * 2 + 0], qa[kk], bk[0], bk[1]);
                mma16816(s[jp * 2 + 1], qa[kk], bk[2], bk[3]);
            }
        }

        const int kvc = kt * 64 + 2 * (lane & 3);
        float mx0 = mrow[0], mx1 = mrow[1];
        #pragma unroll
        for (int j = 0; j < 8; j++) {
            int kv = kvc + j * 8;
            if (kv     >= SEQ) { s[j][0] = -1e30f; s[j][2] = -1e30f; }
            if (kv + 1 >= SEQ) { s[j][1] = -1e30f; s[j][3] = -1e30f; }
            mx0 = fmaxf(mx0, fmaxf(s[j][0], s[j][1]));
            mx1 = fmaxf(mx1, fmaxf(s[j][2], s[j][3]));
        }
        mx0 = fmaxf(mx0, __shfl_xor_sync(0xffffffffu, mx0, 1));
        mx0 = fmaxf(mx0, __shfl_xor_sync(0xffffffffu, mx0, 2));
        mx1 = fmaxf(mx1, __shfl_xor_sync(0xffffffffu, mx1, 1));
        mx1 = fmaxf(mx1, __shfl_xor_sync(0xffffffffu, mx1, 2));

        const float alpha0 = ex2(mrow[0] - mx0);
        const float alpha1 = ex2(mrow[1] - mx1);
        mrow[0] = mx0; mrow[1] = mx1;

        float ls0 = 0.f, ls1 = 0.f;
        uint32_t pa[4][4];
        #pragma unroll
        for (int j = 0; j < 8; j++) {
            float p0 = ex2(s[j][0] - mx0);
            float p1 = ex2(s[j][1] - mx0);
            float p2 = ex2(s[j][2] - mx1);
            float p3 = ex2(s[j][3] - mx1);
            ls0 += p0 + p1;
            ls1 += p2 + p3;
            __half2 h01 = __floats2half2_rn(p0, p1);
            __half2 h23 = __floats2half2_rn(p2, p3);
            pa[j >> 1][(j & 1) * 2 + 0] = *(uint32_t*)&h01;
            pa[j >> 1][(j & 1) * 2 + 1] = *(uint32_t*)&h23;
        }
        ls0 += __shfl_xor_sync(0xffffffffu, ls0, 1);
        ls0 += __shfl_xor_sync(0xffffffffu, ls0, 2);
        ls1 += __shfl_xor_sync(0xffffffffu, ls1, 1);
        ls1 += __shfl_xor_sync(0xffffffffu, ls1, 2);
        lrow[0] = lrow[0] * alpha0 + ls0;
        lrow[1] = lrow[1] * alpha1 + ls1;

        #pragma unroll
        for (int j = 0; j < 8; j++) {
            o[j][0] *= alpha0; o[j][1] *= alpha0;
            o[j][2] *= alpha1; o[j][3] *= alpha1;
        }

        #pragma unroll
        for (int kk = 0; kk < 4; kk++) {
            #pragma unroll
            for (int jp = 0; jp < 4; jp++) {
                uint32_t bv[4];
                uint32_t addr = Vt_u +
                    (uint32_t)((kk * 16 + (grp & 1) * 8 + l8) * LDH
                               + (jp * 2 + (grp >> 1)) * 8) * 2;
                ldsm_x4t(bv, addr);
                mma16816(o[jp * 2 + 0], pa[kk], bv[0], bv[1]);
                mma16816(o[jp * 2 + 1], pa[kk], bv[2], bv[3]);
            }
        }
    }

    const float rinv0 = 1.0f / lrow[0];
    const float rinv1 = 1.0f / lrow[1];
    const int qi0 = q0 + warp * 16 + (lane >> 2);
    const int qi1 = qi0 + 8;
    const int dbase = h * HDIM + 2 * (lane & 3);
    #pragma unroll
    for (int j = 0; j < 8; j++) {
        int d = dbase + j * 8;
        if (qi0 < SEQ) {
            __half2 v = __floats2half2_rn(o[j][0] * rinv0, o[j][1] * rinv0);
            *(__half2*)(g_Oh + (size_t)(b * SEQ + qi0) * EMBED + d) = v;
        }
        if (qi1 < SEQ) {
            __half2 v = __floats2half2_rn(o[j][2] * rinv1, o[j][3] * rinv1);
            *(__half2*)(g_Oh + (size_t)(b * SEQ + qi1) * EMBED + d) = v;
        }
    }
}

// ===========================================================================
// Aux: single fused fp32 -> fp16 conversion over X, Wqkv, Wproj
// ===========================================================================
#define N8_X  ((size_t)MROWS * EMBED / 8)
#define N8_W1 ((size_t)EMBED * QKV_N / 8)
#define N8_W2 ((size_t)EMBED * EMBED / 8)

__global__ void f2h_all_kernel(const float* __restrict__ x,
                               const float* __restrict__ w1,
                               const float* __restrict__ w2)
{
    const size_t ntot = N8_X + N8_W1 + N8_W2;
    for (size_t i = blockIdx.x * blockDim.x + threadIdx.x; i < ntot;
         i += (size_t)gridDim.x * blockDim.x) {
        const float* src;
        __half* dst;
        size_t k;
        if (i < N8_X)             { src = x;  dst = g_Xh;     k = i; }
        else if (i < N8_X + N8_W1){ src = w1; dst = g_Wqkvh;  k = i - N8_X; }
        else                      { src = w2; dst = g_Wprojh; k = i - N8_X - N8_W1; }
        float4 a = ((const float4*)src)[2 * k];
        float4 b = ((const float4*)src)[2 * k + 1];
        __half2 h0 = __floats2half2_rn(a.x, a.y);
        __half2 h1 = __floats2half2_rn(a.z, a.w);
        __half2 h2 = __floats2half2_rn(b.x, b.y);
        __half2 h3 = __floats2half2_rn(b.z, b.w);
        uint4 o;
        o.x = *(uint32_t*)&h0; o.y = *(uint32_t*)&h1;
        o.z = *(uint32_t*)&h2; o.w = *(uint32_t*)&h3;
        ((uint4*)dst)[k] = o;
    }
}

// ===========================================================================
extern "C" void kernel_launch(void* const* d_in, const int* in_sizes, int n_in,
                              void* d_out, int out_size)
{
    (void)in_sizes; (void)n_in; (void)out_size;
    const float* x      = (const float*)d_in[0];
    const float* w_qkv  = (const float*)d_in[1];
    const float* w_proj = (const float*)d_in[2];
    const float* b_proj = (const float*)d_in[3];
    float* out = (float*)d_out;

    cudaFuncSetAttribute(gemm_qkv_kernel,  cudaFuncAttributeMaxDynamicSharedMemorySize, GEMM_SMEM_BYTES);
    cudaFuncSetAttribute(gemm_proj_kernel, cudaFuncAttributeMaxDynamicSharedMemorySize, GEMM_SMEM_BYTES);
    cudaFuncSetAttribute(attn_kernel,      cudaFuncAttributeMaxDynamicSharedMemorySize, (int)ATTN_SMEM);

    __half *dXh, *dWqkvh, *dWprojh, *dOh;
    cudaGetSymbolAddress((void**)&dXh,     g_Xh);
    cudaGetSymbolAddress((void**)&dWqkvh,  g_Wqkvh);
    cudaGetSymbolAddress((void**)&dWprojh, g_Wprojh);
    cudaGetSymbolAddress((void**)&dOh,     g_Oh);

    f2h_all_kernel<<<2048, 256>>>(x, w_qkv, w_proj);

    const int mblocks = (MROWS + BM - 1) / BM;   // 145
    gemm_qkv_kernel<<<dim3(QKV_N / BN, mblocks), 256, GEMM_SMEM_BYTES>>>(dXh, dWqkvh);

    const int qblocks = (SEQ + 127) / 128;       // 5
    attn_kernel<<<dim3(qblocks, BATCH * HEADS), 256, ATTN_SMEM>>>();

    gemm_proj_kernel<<<dim3(EMBED / BN, mblocks), 256, GEMM_SMEM_BYTES>>>(dOh, dWprojh, b_proj, out);
}

// round 13
// speedup vs baseline: 1.0681x; 1.0681x over previous
#include <cuda_runtime.h>
#include <cuda_fp16.h>
#include <cstdint>

#define BATCH   32
#define SEQ     577
#define EMBED   768
#define HEADS   12
#define HDIM    64
#define MROWS   (BATCH * SEQ)        // 18464
#define QKV_N   (3 * EMBED)          // 2304
// log2 domain: Q pre-scaled by ATT_SCALE * log2(e); softmax uses ex2.approx
#define ATT_SCALE_LOG2E 0.1803368801111204f

// ---------------- scratch (module-load allocated, no runtime allocs) -------
__device__ __half g_Qh[(size_t)BATCH * HEADS * SEQ * HDIM];   // [b,h,n,d], pre-scaled
__device__ __half g_Kh[(size_t)BATCH * HEADS * SEQ * HDIM];
__device__ __half g_Vh[(size_t)BATCH * HEADS * SEQ * HDIM];
__device__ __half g_Oh[(size_t)MROWS * EMBED];                // attention out (half)
__device__ __half g_Xh[(size_t)MROWS * EMBED];                // half X
__device__ __half g_Wqkvh[(size_t)EMBED * QKV_N];             // half W_qkv (row-major)
__device__ __half g_Wprojh[(size_t)EMBED * EMBED];            // half W_proj (row-major)

// ---------------- PTX helpers ----------------------------------------------
__device__ __forceinline__ uint32_t smem_u32(const void* p) {
    uint32_t a;
    asm("{ .reg .u64 t; cvta.to.shared.u64 t, %1; cvt.u32.u64 %0, t; }"
        : "=r"(a) : "l"(p));
    return a;
}
__device__ __forceinline__ void cp16(uint32_t dst, const void* src, bool pred) {
    int sz = pred ? 16 : 0;
    asm volatile("cp.async.cg.shared.global [%0], [%1], 16, %2;\n"
                 :: "r"(dst), "l"(src), "r"(sz));
}
#define CP_COMMIT() asm volatile("cp.async.commit_group;\n" ::: "memory")
#define CP_WAIT1()  asm volatile("cp.async.wait_group 1;\n" ::: "memory")
#define CP_WAIT0()  asm volatile("cp.async.wait_group 0;\n" ::: "memory")

__device__ __forceinline__ void ldsm_x4(uint32_t (&r)[4], uint32_t addr) {
    asm volatile("ldmatrix.sync.aligned.m8n8.x4.shared.b16 {%0,%1,%2,%3}, [%4];"
                 : "=r"(r[0]), "=r"(r[1]), "=r"(r[2]), "=r"(r[3]) : "r"(addr));
}
__device__ __forceinline__ void ldsm_x4t(uint32_t (&r)[4], uint32_t addr) {
    asm volatile("ldmatrix.sync.aligned.m8n8.x4.trans.shared.b16 {%0,%1,%2,%3}, [%4];"
                 : "=r"(r[0]), "=r"(r[1]), "=r"(r[2]), "=r"(r[3]) : "r"(addr));
}
__device__ __forceinline__ void mma16816(float (&d)[4], const uint32_t (&a)[4],
                                         uint32_t b0, uint32_t b1) {
    asm volatile("mma.sync.aligned.m16n8k16.row.col.f32.f16.f16.f32 "
                 "{%0,%1,%2,%3}, {%4,%5,%6,%7}, {%8,%9}, {%0,%1,%2,%3};"
                 : "+f"(d[0]), "+f"(d[1]), "+f"(d[2]), "+f"(d[3])
                 : "r"(a[0]), "r"(a[1]), "r"(a[2]), "r"(a[3]), "r"(b0), "r"(b1));
}
__device__ __forceinline__ float ex2(float x) {
    float r;
    asm("ex2.approx.ftz.f32 %0, %1;" : "=f"(r) : "f"(x));
    return r;
}

// ---------------- GEMM tiling (raw mma, fp16) — R11 config ------------------
// BM=128, BN=128, BK=64; 8 warps as 2(m) x 4(n); warp tile 64x32.
// 3-stage pipeline, wait_group 1 + one __syncthreads per K-iteration.
#define BM 128
#define BN 128
#define BK 64
#define LDA 72
#define A_ST (BM * LDA)
#define B_ST_B 16384
#define KTILES (EMBED / BK)          // 12
#define GEMM_SMEM_BYTES (3 * (A_ST * 2 + B_ST_B))   // 104448

template <typename EPI>
__device__ __forceinline__ void gemm_mma(
    const __half* __restrict__ Ag, const __half* __restrict__ Bg, int ldb_g,
    int m0, int n0, bool mtail, EPI epi)
{
    extern __shared__ __half smh[];
    uint32_t sA_u = smem_u32(smh);
    uint32_t sB_u = sA_u + 3 * A_ST * 2;

    const int tid  = threadIdx.x;
    const int warp = tid >> 5;
    const int lane = tid & 31;
    const int wm   = warp >> 2;      // 0..1
    const int wn   = warp & 3;       // 0..3

    auto issue = [&](int kt, int st) {
        const int k0 = kt * BK;
        #pragma unroll
        for (int j = 0; j < 4; j++) {
            int i  = tid + j * 256;
            int r  = i >> 3;
            int ch = i & 7;
            int gm = m0 + r;
            bool p = !mtail || (gm < MROWS);
            cp16(sA_u + (uint32_t)(st * A_ST + r * LDA + ch * 8) * 2,
                 Ag + (size_t)gm * EMBED + k0 + ch * 8, p);
        }
        #pragma unroll
        for (int j = 0; j < 4; j++) {
            int i  = tid + j * 256;
            int r  = i >> 4;
            int c  = i & 15;
            cp16(sB_u + (uint32_t)(st * B_ST_B + r * 256 + ((c ^ (r & 7)) << 4)),
                 Bg + (size_t)(k0 + r) * ldb_g + n0 + c * 8, true);
        }
        CP_COMMIT();
    };

    float acc[4][4][4];
    #pragma unroll
    for (int i = 0; i < 4; i++)
        #pragma unroll
        for (int j = 0; j < 4; j++)
            #pragma unroll
            for (int c = 0; c < 4; c++) acc[i][j][c] = 0.f;

    issue(0, 0);
    issue(1, 1);

    const int l16 = lane & 15;
    const int lh  = lane >> 4;

    for (int it = 0; it < KTILES; it++) {
        if (it == KTILES - 1) CP_WAIT0(); else CP_WAIT1();
        __syncthreads();

        const int st = it % 3;
        const uint32_t aBase = sA_u + (uint32_t)(st * A_ST) * 2;
        const uint32_t bBase = sB_u + (uint32_t)(st * B_ST_B);

        // kk = 0 peeled: fragments loaded before next tile's cp.async issue
        {
            uint32_t am[4][4];
            #pragma unroll
            for (int i = 0; i < 4; i++) {
                int row = wm * 64 + i * 16 + l16;
                ldsm_x4(am[i], aBase + (uint32_t)(row * LDA + lh * 8) * 2);
            }
            uint32_t bf[2][4];
            #pragma unroll
            for (int jj = 0; jj < 2; jj++) {
                int r = l16;
                int c = wn * 4 + jj * 2 + lh;
                ldsm_x4t(bf[jj], bBase + (uint32_t)(r * 256 + ((c ^ (r & 7)) << 4)));
            }
            if (it + 2 < KTILES) issue(it + 2, (it + 2) % 3);
            #pragma unroll
            for (int i = 0; i < 4; i++) {
                #pragma unroll
                for (int jj = 0; jj < 2; jj++) {
                    mma16816(acc[i][jj * 2 + 0], am[i], bf[jj][0], bf[jj][1]);
                    mma16816(acc[i][jj * 2 + 1], am[i], bf[jj][2], bf[jj][3]);
                }
            }
        }
        #pragma unroll
        for (int kk = 1; kk < 4; kk++) {
            uint32_t am[4][4];
            #pragma unroll
            for (int i = 0; i < 4; i++) {
                int row = wm * 64 + i * 16 + l16;
                ldsm_x4(am[i], aBase + (uint32_t)(row * LDA + kk * 16 + lh * 8) * 2);
            }
            uint32_t bf[2][4];
            #pragma unroll
            for (int jj = 0; jj < 2; jj++) {
                int r = kk * 16 + l16;
                int c = wn * 4 + jj * 2 + lh;
                ldsm_x4t(bf[jj], bBase + (uint32_t)(r * 256 + ((c ^ (r & 7)) << 4)));
            }
            #pragma unroll
            for (int i = 0; i < 4; i++) {
                #pragma unroll
                for (int jj = 0; jj < 2; jj++) {
                    mma16816(acc[i][jj * 2 + 0], am[i], bf[jj][0], bf[jj][1]);
                    mma16816(acc[i][jj * 2 + 1], am[i], bf[jj][2], bf[jj][3]);
                }
            }
        }
    }

    const int row0 = m0 + wm * 64 + (lane >> 2);
    const int gnb  = n0 + wn * 32 + 2 * (lane & 3);
    #pragma unroll
    for (int i = 0; i < 4; i++) {
        #pragma unroll
        for (int j = 0; j < 4; j++) {
            int gn = gnb + j * 8;
            epi(row0 + i * 16,     gn, acc[i][j][0], acc[i][j][1]);
            epi(row0 + i * 16 + 8, gn, acc[i][j][2], acc[i][j][3]);
        }
    }
}

// ===========================================================================
// Kernel 1: QKV GEMM + scatter epilogue (Q scaled by ATT_SCALE*log2e)
// ===========================================================================
__global__ void __launch_bounds__(256, 2) gemm_qkv_kernel(const __half* __restrict__ X,
                                                          const __half* __restrict__ W)
{
    const int m0 = blockIdx.y * BM;
    const int n0 = blockIdx.x * BN;
    const bool mtail = (m0 + BM > MROWS);

    gemm_mma(X, W, QKV_N, m0, n0, mtail,
        [&](int gm, int gn, float v0, float v1) {
            if (gm >= MROWS) return;
            int b   = gm / SEQ;
            int tok = gm - b * SEQ;
            int s   = gn / EMBED;
            int rem = gn - s * EMBED;
            int h   = rem >> 6;
            int d   = rem & 63;
            size_t idx = ((size_t)(b * HEADS + h) * SEQ + tok) * HDIM + d;
            if (s == 0) {
                *(__half2*)(g_Qh + idx) =
                    __floats2half2_rn(v0 * ATT_SCALE_LOG2E, v1 * ATT_SCALE_LOG2E);
            } else if (s == 1) {
                *(__half2*)(g_Kh + idx) = __floats2half2_rn(v0, v1);
            } else {
                *(__half2*)(g_Vh + idx) = __floats2half2_rn(v0, v1);
            }
        });
}

// ===========================================================================
// Kernel 3: projection GEMM.  out = g_Oh @ Wp + bias
// ===========================================================================
__global__ void __launch_bounds__(256, 2) gemm_proj_kernel(const __half* __restrict__ A,
                                                           const __half* __restrict__ W,
                                                           const float* __restrict__ bias,
                                                           float* __restrict__ out)
{
    const int m0 = blockIdx.y * BM;
    const int n0 = blockIdx.x * BN;
    const bool mtail = (m0 + BM > MROWS);

    gemm_mma(A, W, EMBED, m0, n0, mtail,
        [&](int gm, int gn, float v0, float v1) {
            if (gm >= MROWS) return;
            float2 v;
            v.x = v0 + bias[gn];
            v.y = v1 + bias[gn + 1];
            *(float2*)(out + (size_t)gm * EMBED + gn) = v;
        });
}

// ===========================================================================
// Kernel 2: flash attention, FA2-style; x4 ldsm batching, exp2-domain softmax
// ===========================================================================
#define KV_TILES ((SEQ + 63) / 64)                 // 10
#define LDH 72
#define KV_TILE_H (64 * LDH)
#define Q_TILE_H  (128 * LDH)
#define ATTN_SMEM ((Q_TILE_H + 4 * KV_TILE_H) * 2) // 55296 B

__global__ void __launch_bounds__(256) attn_kernel()
{
    extern __shared__ __half smh[];
    const int tid  = threadIdx.x;
    const int warp = tid >> 5;
    const int lane = tid & 31;
    const int bh   = blockIdx.y;
    const int b    = bh / HEADS;
    const int h    = bh - b * HEADS;
    const int q0   = blockIdx.x * 128;

    const __half* Qg = g_Qh + (size_t)bh * SEQ * HDIM;
    const __half* Kg = g_Kh + (size_t)bh * SEQ * HDIM;
    const __half* Vg = g_Vh + (size_t)bh * SEQ * HDIM;

    uint32_t Qs_u = smem_u32(smh);
    uint32_t Ks_u = Qs_u + Q_TILE_H * 2;
    uint32_t Vs_u = Ks_u + 2 * KV_TILE_H * 2;

    auto issue_kv = [&](int kt, int st) {
        const int kbase = kt * 64;
        #pragma unroll
        for (int j = 0; j < 2; j++) {
            int i  = tid + j * 256;
            int r  = i >> 3;
            int c8 = (i & 7) << 3;
            int ki = kbase + r;
            bool p = ki < SEQ;
            uint32_t off = (uint32_t)(st * KV_TILE_H + r * LDH + c8) * 2;
            cp16(Ks_u + off, Kg + (size_t)ki * HDIM + c8, p);
            cp16(Vs_u + off, Vg + (size_t)ki * HDIM + c8, p);
        }
        CP_COMMIT();
    };

    #pragma unroll
    for (int j = 0; j < 4; j++) {
        int i  = tid + j * 256;
        int r  = i >> 3;
        int c8 = (i & 7) << 3;
        int qi = q0 + r;
        cp16(Qs_u + (uint32_t)(r * LDH + c8) * 2, Qg + (size_t)qi * HDIM + c8, qi < SEQ);
    }
    issue_kv(0, 0);

    CP_WAIT0();
    __syncthreads();

    uint32_t qa[4][4];
    {
        const int l8  = lane & 7;
        const int sel = lane >> 3;
        #pragma unroll
        for (int kk = 0; kk < 4; kk++) {
            uint32_t addr = Qs_u +
                (uint32_t)((warp * 16 + (sel & 1) * 8 + l8) * LDH + kk * 16 + (sel >> 1) * 8) * 2;
            ldsm_x4(qa[kk], addr);
        }
    }
    if (KV_TILES > 1) issue_kv(1, 1);

    float o[8][4];
    #pragma unroll
    for (int j = 0; j < 8; j++)
        #pragma unroll
        for (int c = 0; c < 4; c++) o[j][c] = 0.f;
    float mrow[2] = {-1e30f, -1e30f};
    float lrow[2] = {0.f, 0.f};

    const int l8  = lane & 7;
    const int grp = lane >> 3;       // 0..3

    for (int kt = 0; kt < KV_TILES; kt++) {
        const int st = kt & 1;
        if (kt > 0) {
            CP_WAIT0();
            __syncthreads();
            if (kt + 1 < KV_TILES) issue_kv(kt + 1, st ^ 1);
        }
        const uint32_t Kt_u = Ks_u + (uint32_t)(st * KV_TILE_H) * 2;
        const uint32_t Vt_u = Vs_u + (uint32_t)(st * KV_TILE_H) * 2;

        float s[8][4];
        #pragma unroll
        for (int j = 0; j < 8; j++)
            #pragma unroll
            for (int c = 0; c < 4; c++) s[j][c] = 0.f;

        #pragma unroll
        for (int kk = 0; kk < 4; kk++) {
            #pragma unroll
            for (int jp = 0; jp < 4; jp++) {
                uint32_t bk[4];
                uint32_t addr = Kt_u +
                    (uint32_t)(((jp * 2 + (grp >> 1)) * 8 + l8) * LDH
                               + kk * 16 + (grp & 1) * 8) * 2;
                ldsm_x4(bk, addr);
                mma16816(s[jp * 2 + 0], qa[kk], bk[0], bk[1]);
                mma16816(s[jp * 2 + 1], qa[kk], bk[2], bk[3]);
            }
        }

        const int kvc = kt * 64 + 2 * (lane & 3);
        float mx0 = mrow[0], mx1 = mrow[1];
        #pragma unroll
        for (int j = 0; j < 8; j++) {
            int kv = kvc + j * 8;
            if (kv     >= SEQ) { s[j][0] = -1e30f; s[j][2] = -1e30f; }
            if (kv + 1 >= SEQ) { s[j][1] = -1e30f; s[j][3] = -1e30f; }
            mx0 = fmaxf(mx0, fmaxf(s[j][0], s[j][1]));
            mx1 = fmaxf(mx1, fmaxf(s[j][2], s[j][3]));
        }
        mx0 = fmaxf(mx0, __shfl_xor_sync(0xffffffffu, mx0, 1));
        mx0 = fmaxf(mx0, __shfl_xor_sync(0xffffffffu, mx0, 2));
        mx1 = fmaxf(mx1, __shfl_xor_sync(0xffffffffu, mx1, 1));
        mx1 = fmaxf(mx1, __shfl_xor_sync(0xffffffffu, mx1, 2));

        const float alpha0 = ex2(mrow[0] - mx0);
        const float alpha1 = ex2(mrow[1] - mx1);
        mrow[0] = mx0; mrow[1] = mx1;

        float ls0 = 0.f, ls1 = 0.f;
        uint32_t pa[4][4];
        #pragma unroll
        for (int j = 0; j < 8; j++) {
            float p0 = ex2(s[j][0] - mx0);
            float p1 = ex2(s[j][1] - mx0);
            float p2 = ex2(s[j][2] - mx1);
            float p3 = ex2(s[j][3] - mx1);
            ls0 += p0 + p1;
            ls1 += p2 + p3;
            __half2 h01 = __floats2half2_rn(p0, p1);
            __half2 h23 = __floats2half2_rn(p2, p3);
            pa[j >> 1][(j & 1) * 2 + 0] = *(uint32_t*)&h01;
            pa[j >> 1][(j & 1) * 2 + 1] = *(uint32_t*)&h23;
        }
        ls0 += __shfl_xor_sync(0xffffffffu, ls0, 1);
        ls0 += __shfl_xor_sync(0xffffffffu, ls0, 2);
        ls1 += __shfl_xor_sync(0xffffffffu, ls1, 1);
        ls1 += __shfl_xor_sync(0xffffffffu, ls1, 2);
        lrow[0] = lrow[0] * alpha0 + ls0;
        lrow[1] = lrow[1] * alpha1 + ls1;

        #pragma unroll
        for (int j = 0; j < 8; j++) {
            o[j][0] *= alpha0; o[j][1] *= alpha0;
            o[j][2] *= alpha1; o[j][3] *= alpha1;
        }

        #pragma unroll
        for (int kk = 0; kk < 4; kk++) {
            #pragma unroll
            for (int jp = 0; jp < 4; jp++) {
                uint32_t bv[4];
                uint32_t addr = Vt_u +
                    (uint32_t)((kk * 16 + (grp & 1) * 8 + l8) * LDH
                               + (jp * 2 + (grp >> 1)) * 8) * 2;
                ldsm_x4t(bv, addr);
                mma16816(o[jp * 2 + 0], pa[kk], bv[0], bv[1]);
                mma16816(o[jp * 2 + 1], pa[kk], bv[2], bv[3]);
            }
        }
    }

    const float rinv0 = 1.0f / lrow[0];
    const float rinv1 = 1.0f / lrow[1];
    const int qi0 = q0 + warp * 16 + (lane >> 2);
    const int qi1 = qi0 + 8;
    const int dbase = h * HDIM + 2 * (lane & 3);
    #pragma unroll
    for (int j = 0; j < 8; j++) {
        int d = dbase + j * 8;
        if (qi0 < SEQ) {
            __half2 v = __floats2half2_rn(o[j][0] * rinv0, o[j][1] * rinv0);
            *(__half2*)(g_Oh + (size_t)(b * SEQ + qi0) * EMBED + d) = v;
        }
        if (qi1 < SEQ) {
            __half2 v = __floats2half2_rn(o[j][2] * rinv1, o[j][3] * rinv1);
            *(__half2*)(g_Oh + (size_t)(b * SEQ + qi1) * EMBED + d) = v;
        }
    }
}

// ===========================================================================
// Aux: fused fp32->fp16 conversion, MLP-4 version (4 LDG.128 in flight)
// ===========================================================================
#define N8_X  ((size_t)MROWS * EMBED / 8)
#define N8_W1 ((size_t)EMBED * QKV_N / 8)
#define N8_W2 ((size_t)EMBED * EMBED / 8)
#define N8_TOT (N8_X + N8_W1 + N8_W2)

__device__ __forceinline__ void f2h_one(const float* __restrict__ src,
                                        __half* __restrict__ dst, size_t k)
{
    float4 a = ((const float4*)src)[2 * k];
    float4 b = ((const float4*)src)[2 * k + 1];
    __half2 h0 = __floats2half2_rn(a.x, a.y);
    __half2 h1 = __floats2half2_rn(a.z, a.w);
    __half2 h2 = __floats2half2_rn(b.x, b.y);
    __half2 h3 = __floats2half2_rn(b.z, b.w);
    uint4 o;
    o.x = *(uint32_t*)&h0; o.y = *(uint32_t*)&h1;
    o.z = *(uint32_t*)&h2; o.w = *(uint32_t*)&h3;
    ((uint4*)dst)[k] = o;
}

__device__ __forceinline__ void f2h_route(size_t i, const float* __restrict__ x,
                                          const float* __restrict__ w1,
                                          const float* __restrict__ w2,
                                          const float*& src, __half*& dst, size_t& k)
{
    if (i < N8_X)              { src = x;  dst = g_Xh;     k = i; }
    else if (i < N8_X + N8_W1) { src = w1; dst = g_Wqkvh;  k = i - N8_X; }
    else                       { src = w2; dst = g_Wprojh; k = i - N8_X - N8_W1; }
}

__global__ void __launch_bounds__(256) f2h_all_kernel(const float* __restrict__ x,
                                                      const float* __restrict__ w1,
                                                      const float* __restrict__ w2)
{
    const size_t stride = (size_t)gridDim.x * blockDim.x;
    size_t i = blockIdx.x * blockDim.x + threadIdx.x;

    // main: 2 regions per iteration -> 4 independent LDG.128 in flight
    for (; i + stride < N8_TOT; i += 2 * stride) {
        const float *s0, *s1;
        __half *d0, *d1;
        size_t k0, k1;
        f2h_route(i,          x, w1, w2, s0, d0, k0);
        f2h_route(i + stride, x, w1, w2, s1, d1, k1);
        float4 a0 = ((const float4*)s0)[2 * k0];
        float4 b0 = ((const float4*)s0)[2 * k0 + 1];
        float4 a1 = ((const float4*)s1)[2 * k1];
        float4 b1 = ((const float4*)s1)[2 * k1 + 1];
        {
            __half2 h0 = __floats2half2_rn(a0.x, a0.y);
            __half2 h1 = __floats2half2_rn(a0.z, a0.w);
            __half2 h2 = __floats2half2_rn(b0.x, b0.y);
            __half2 h3 = __floats2half2_rn(b0.z, b0.w);
            uint4 o;
            o.x = *(uint32_t*)&h0; o.y = *(uint32_t*)&h1;
            o.z = *(uint32_t*)&h2; o.w = *(uint32_t*)&h3;
            ((uint4*)d0)[k0] = o;
        }
        {
            __half2 h0 = __floats2half2_rn(a1.x, a1.y);
            __half2 h1 = __floats2half2_rn(a1.z, a1.w);
            __half2 h2 = __floats2half2_rn(b1.x, b1.y);
            __half2 h3 = __floats2half2_rn(b1.z, b1.w);
            uint4 o;
            o.x = *(uint32_t*)&h0; o.y = *(uint32_t*)&h1;
            o.z = *(uint32_t*)&h2; o.w = *(uint32_t*)&h3;
            ((uint4*)d1)[k1] = o;
        }
    }
    // tail
    for (; i < N8_TOT; i += stride) {
        const float* s;
        __half* d;
        size_t k;
        f2h_route(i, x, w1, w2, s, d, k);
        f2h_one(s, d, k);
    }
}

// ===========================================================================
extern "C" void kernel_launch(void* const* d_in, const int* in_sizes, int n_in,
                              void* d_out, int out_size)
{
    (void)in_sizes; (void)n_in; (void)out_size;
    const float* x      = (const float*)d_in[0];
    const float* w_qkv  = (const float*)d_in[1];
    const float* w_proj = (const float*)d_in[2];
    const float* b_proj = (const float*)d_in[3];
    float* out = (float*)d_out;

    cudaFuncSetAttribute(gemm_qkv_kernel,  cudaFuncAttributeMaxDynamicSharedMemorySize, GEMM_SMEM_BYTES);
    cudaFuncSetAttribute(gemm_proj_kernel, cudaFuncAttributeMaxDynamicSharedMemorySize, GEMM_SMEM_BYTES);
    cudaFuncSetAttribute(attn_kernel,      cudaFuncAttributeMaxDynamicSharedMemorySize, (int)ATTN_SMEM);

    __half *dXh, *dWqkvh, *dWprojh, *dOh;
    cudaGetSymbolAddress((void**)&dXh,     g_Xh);
    cudaGetSymbolAddress((void**)&dWqkvh,  g_Wqkvh);
    cudaGetSymbolAddress((void**)&dWprojh, g_Wprojh);
    cudaGetSymbolAddress((void**)&dOh,     g_Oh);

    f2h_all_kernel<<<2048, 256>>>(x, w_qkv, w_proj);

    const int mblocks = (MROWS + BM - 1) / BM;   // 145
    gemm_qkv_kernel<<<dim3(QKV_N / BN, mblocks), 256, GEMM_SMEM_BYTES>>>(dXh, dWqkvh);

    const int qblocks = (SEQ + 127) / 128;       // 5
    attn_kernel<<<dim3(qblocks, BATCH * HEADS), 256, ATTN_SMEM>>>();

    gemm_proj_kernel<<<dim3(EMBED / BN, mblocks), 256, GEMM_SMEM_BYTES>>>(dOh, dWprojh, b_proj, out);
}

// round 14
// speedup vs baseline: 1.1277x; 1.0558x over previous
#include <cuda_runtime.h>
#include <cuda_fp16.h>
#include <cstdint>

#define BATCH   32
#define SEQ     577
#define EMBED   768
#define HEADS   12
#define HDIM    64
#define MROWS   (BATCH * SEQ)        // 18464
#define QKV_N   (3 * EMBED)          // 2304
// log2 domain: Q pre-scaled by ATT_SCALE * log2(e); softmax uses ex2.approx
#define ATT_SCALE_LOG2E 0.1803368801111204f

// ---------------- scratch (module-load allocated, no runtime allocs) -------
__device__ __half g_Qh[(size_t)BATCH * HEADS * SEQ * HDIM];   // [b,h,n,d], pre-scaled
__device__ __half g_Kh[(size_t)BATCH * HEADS * SEQ * HDIM];
__device__ __half g_Vh[(size_t)BATCH * HEADS * SEQ * HDIM];
__device__ __half g_Oh[(size_t)MROWS * EMBED];                // attention out (half)
__device__ __half g_Xh[(size_t)MROWS * EMBED];                // half X
__device__ __half g_Wqkvh[(size_t)EMBED * QKV_N];             // half W_qkv (row-major)
__device__ __half g_Wprojh[(size_t)EMBED * EMBED];            // half W_proj (row-major)

// ---------------- PTX helpers ----------------------------------------------
__device__ __forceinline__ uint32_t smem_u32(const void* p) {
    uint32_t a;
    asm("{ .reg .u64 t; cvta.to.shared.u64 t, %1; cvt.u32.u64 %0, t; }"
        : "=r"(a) : "l"(p));
    return a;
}
__device__ __forceinline__ void cp16(uint32_t dst, const void* src, bool pred) {
    int sz = pred ? 16 : 0;
    asm volatile("cp.async.cg.shared.global [%0], [%1], 16, %2;\n"
                 :: "r"(dst), "l"(src), "r"(sz));
}
#define CP_COMMIT() asm volatile("cp.async.commit_group;\n" ::: "memory")
#define CP_WAIT1()  asm volatile("cp.async.wait_group 1;\n" ::: "memory")
#define CP_WAIT0()  asm volatile("cp.async.wait_group 0;\n" ::: "memory")

__device__ __forceinline__ void ldsm_x4(uint32_t (&r)[4], uint32_t addr) {
    asm volatile("ldmatrix.sync.aligned.m8n8.x4.shared.b16 {%0,%1,%2,%3}, [%4];"
                 : "=r"(r[0]), "=r"(r[1]), "=r"(r[2]), "=r"(r[3]) : "r"(addr));
}
__device__ __forceinline__ void ldsm_x4t(uint32_t (&r)[4], uint32_t addr) {
    asm volatile("ldmatrix.sync.aligned.m8n8.x4.trans.shared.b16 {%0,%1,%2,%3}, [%4];"
                 : "=r"(r[0]), "=r"(r[1]), "=r"(r[2]), "=r"(r[3]) : "r"(addr));
}
__device__ __forceinline__ void mma16816(float (&d)[4], const uint32_t (&a)[4],
                                         uint32_t b0, uint32_t b1) {
    asm volatile("mma.sync.aligned.m16n8k16.row.col.f32.f16.f16.f32 "
                 "{%0,%1,%2,%3}, {%4,%5,%6,%7}, {%8,%9}, {%0,%1,%2,%3};"
                 : "+f"(d[0]), "+f"(d[1]), "+f"(d[2]), "+f"(d[3])
                 : "r"(a[0]), "r"(a[1]), "r"(a[2]), "r"(a[3]), "r"(b0), "r"(b1));
}
__device__ __forceinline__ float ex2(float x) {
    float r;
    asm("ex2.approx.ftz.f32 %0, %1;" : "=f"(r) : "f"(x));
    return r;
}

// ---------------- GEMM tiling (raw mma, fp16) — R11 config ------------------
// BM=128, BN=128, BK=64; 8 warps as 2(m) x 4(n); warp tile 64x32.
// 3-stage pipeline, wait_group 1 + one __syncthreads per K-iteration.
#define BM 128
#define BN 128
#define BK 64
#define LDA 72
#define A_ST (BM * LDA)
#define B_ST_B 16384
#define KTILES (EMBED / BK)          // 12
#define GEMM_SMEM_BYTES (3 * (A_ST * 2 + B_ST_B))   // 104448

__device__ __forceinline__ void gemm_mma(
    const __half* __restrict__ Ag, const __half* __restrict__ Bg, int ldb_g,
    int m0, int n0, bool mtail, float (&acc)[4][4][4])
{
    extern __shared__ __half smh[];
    uint32_t sA_u = smem_u32(smh);
    uint32_t sB_u = sA_u + 3 * A_ST * 2;

    const int tid  = threadIdx.x;
    const int warp = tid >> 5;
    const int lane = tid & 31;
    const int wm   = warp >> 2;      // 0..1
    const int wn   = warp & 3;       // 0..3

    auto issue = [&](int kt, int st) {
        const int k0 = kt * BK;
        #pragma unroll
        for (int j = 0; j < 4; j++) {
            int i  = tid + j * 256;
            int r  = i >> 3;
            int ch = i & 7;
            int gm = m0 + r;
            bool p = !mtail || (gm < MROWS);
            cp16(sA_u + (uint32_t)(st * A_ST + r * LDA + ch * 8) * 2,
                 Ag + (size_t)gm * EMBED + k0 + ch * 8, p);
        }
        #pragma unroll
        for (int j = 0; j < 4; j++) {
            int i  = tid + j * 256;
            int r  = i >> 4;
            int c  = i & 15;
            cp16(sB_u + (uint32_t)(st * B_ST_B + r * 256 + ((c ^ (r & 7)) << 4)),
                 Bg + (size_t)(k0 + r) * ldb_g + n0 + c * 8, true);
        }
        CP_COMMIT();
    };

    #pragma unroll
    for (int i = 0; i < 4; i++)
        #pragma unroll
        for (int j = 0; j < 4; j++)
            #pragma unroll
            for (int c = 0; c < 4; c++) acc[i][j][c] = 0.f;

    issue(0, 0);
    issue(1, 1);

    const int l16 = lane & 15;
    const int lh  = lane >> 4;

    for (int it = 0; it < KTILES; it++) {
        if (it == KTILES - 1) CP_WAIT0(); else CP_WAIT1();
        __syncthreads();

        const int st = it % 3;
        const uint32_t aBase = sA_u + (uint32_t)(st * A_ST) * 2;
        const uint32_t bBase = sB_u + (uint32_t)(st * B_ST_B);

        // kk = 0 peeled: fragments loaded before next tile's cp.async issue
        {
            uint32_t am[4][4];
            #pragma unroll
            for (int i = 0; i < 4; i++) {
                int row = wm * 64 + i * 16 + l16;
                ldsm_x4(am[i], aBase + (uint32_t)(row * LDA + lh * 8) * 2);
            }
            uint32_t bf[2][4];
            #pragma unroll
            for (int jj = 0; jj < 2; jj++) {
                int r = l16;
                int c = wn * 4 + jj * 2 + lh;
                ldsm_x4t(bf[jj], bBase + (uint32_t)(r * 256 + ((c ^ (r & 7)) << 4)));
            }
            if (it + 2 < KTILES) issue(it + 2, (it + 2) % 3);
            #pragma unroll
            for (int i = 0; i < 4; i++) {
                #pragma unroll
                for (int jj = 0; jj < 2; jj++) {
                    mma16816(acc[i][jj * 2 + 0], am[i], bf[jj][0], bf[jj][1]);
                    mma16816(acc[i][jj * 2 + 1], am[i], bf[jj][2], bf[jj][3]);
                }
            }
        }
        #pragma unroll
        for (int kk = 1; kk < 4; kk++) {
            uint32_t am[4][4];
            #pragma unroll
            for (int i = 0; i < 4; i++) {
                int row = wm * 64 + i * 16 + l16;
                ldsm_x4(am[i], aBase + (uint32_t)(row * LDA + kk * 16 + lh * 8) * 2);
            }
            uint32_t bf[2][4];
            #pragma unroll
            for (int jj = 0; jj < 2; jj++) {
                int r = kk * 16 + l16;
                int c = wn * 4 + jj * 2 + lh;
                ldsm_x4t(bf[jj], bBase + (uint32_t)(r * 256 + ((c ^ (r & 7)) << 4)));
            }
            #pragma unroll
            for (int i = 0; i < 4; i++) {
                #pragma unroll
                for (int jj = 0; jj < 2; jj++) {
                    mma16816(acc[i][jj * 2 + 0], am[i], bf[jj][0], bf[jj][1]);
                    mma16816(acc[i][jj * 2 + 1], am[i], bf[jj][2], bf[jj][3]);
                }
            }
        }
    }
}

// ===========================================================================
// Kernel 1: QKV GEMM; epilogue stages C through smem (half, Q pre-scaled)
// then scatters in coalesced 16B chunks. n0 block lies in ONE q/k/v segment.
// ===========================================================================
#define LDC2 136   // smem halves per row for staged C tile

__global__ void __launch_bounds__(256, 2) gemm_qkv_kernel(const __half* __restrict__ X,
                                                          const __half* __restrict__ W)
{
    extern __shared__ __half smh[];
    const int m0 = blockIdx.y * BM;
    const int n0 = blockIdx.x * BN;
    const bool mtail = (m0 + BM > MROWS);

    float acc[4][4][4];
    gemm_mma(X, W, QKV_N, m0, n0, mtail, acc);

    __syncthreads();   // stages dead; reuse smem for C tile

    const int tid  = threadIdx.x;
    const int warp = tid >> 5;
    const int lane = tid & 31;
    const int wm   = warp >> 2;
    const int wn   = warp & 3;

    const int s   = n0 / EMBED;                 // entire block in one segment
    const float sc = (s == 0) ? ATT_SCALE_LOG2E : 1.0f;
    __half* base = (s == 0) ? g_Qh : (s == 1) ? g_Kh : g_Vh;
    const int rem0 = n0 - s * EMBED;

    // stage: acc -> smem half (conflict-free: row stride 272B)
    {
        const int r0 = wm * 64 + (lane >> 2);
        const int c0 = wn * 32 + 2 * (lane & 3);
        #pragma unroll
        for (int i = 0; i < 4; i++) {
            #pragma unroll
            for (int j = 0; j < 4; j++) {
                int c = c0 + j * 8;
                *(__half2*)(smh + (r0 + i * 16) * LDC2 + c) =
                    __floats2half2_rn(acc[i][j][0] * sc, acc[i][j][1] * sc);
                *(__half2*)(smh + (r0 + i * 16 + 8) * LDC2 + c) =
                    __floats2half2_rn(acc[i][j][2] * sc, acc[i][j][3] * sc);
            }
        }
    }
    __syncthreads();

    // coalesced scatter: 128 rows x 16 chunks of 16B
    #pragma unroll
    for (int k = 0; k < 8; k++) {
        int idx = tid + k * 256;
        int r = idx >> 4;
        int c = idx & 15;
        int gm = m0 + r;
        if (gm >= MROWS) continue;
        int rem = rem0 + c * 8;
        int h = rem >> 6;
        int d = rem & 63;
        int b = gm / SEQ;
        int tok = gm - b * SEQ;
        *(uint4*)(base + ((size_t)(b * HEADS + h) * SEQ + tok) * HDIM + d) =
            *(const uint4*)(smh + r * LDC2 + c * 8);
    }
}

// ===========================================================================
// Kernel 3: projection GEMM.  out = g_Oh @ Wp + bias  (float2 = full sectors)
// ===========================================================================
__global__ void __launch_bounds__(256, 2) gemm_proj_kernel(const __half* __restrict__ A,
                                                           const __half* __restrict__ W,
                                                           const float* __restrict__ bias,
                                                           float* __restrict__ out)
{
    const int m0 = blockIdx.y * BM;
    const int n0 = blockIdx.x * BN;
    const bool mtail = (m0 + BM > MROWS);

    float acc[4][4][4];
    gemm_mma(g_Oh + 0, W, EMBED, m0, n0, mtail, acc);
    (void)A;

    const int tid  = threadIdx.x;
    const int warp = tid >> 5;
    const int lane = tid & 31;
    const int wm   = warp >> 2;
    const int wn   = warp & 3;

    const int row0 = m0 + wm * 64 + (lane >> 2);
    const int gnb  = n0 + wn * 32 + 2 * (lane & 3);
    #pragma unroll
    for (int i = 0; i < 4; i++) {
        #pragma unroll
        for (int j = 0; j < 4; j++) {
            int gn = gnb + j * 8;
            int gm0 = row0 + i * 16;
            if (gm0 < MROWS) {
                float2 v;
                v.x = acc[i][j][0] + bias[gn];
                v.y = acc[i][j][1] + bias[gn + 1];
                *(float2*)(out + (size_t)gm0 * EMBED + gn) = v;
            }
            if (gm0 + 8 < MROWS) {
                float2 v;
                v.x = acc[i][j][2] + bias[gn];
                v.y = acc[i][j][3] + bias[gn + 1];
                *(float2*)(out + (size_t)(gm0 + 8) * EMBED + gn) = v;
            }
        }
    }
}

// ===========================================================================
// Kernel 2: flash attention; epilogue staged through smem for coalesced O
// ===========================================================================
#define KV_TILES ((SEQ + 63) / 64)                 // 10
#define LDH 72
#define KV_TILE_H (64 * LDH)
#define Q_TILE_H  (128 * LDH)
#define ATTN_SMEM ((Q_TILE_H + 4 * KV_TILE_H) * 2) // 55296 B

__global__ void __launch_bounds__(256) attn_kernel()
{
    extern __shared__ __half smh[];
    const int tid  = threadIdx.x;
    const int warp = tid >> 5;
    const int lane = tid & 31;
    const int bh   = blockIdx.y;
    const int b    = bh / HEADS;
    const int h    = bh - b * HEADS;
    const int q0   = blockIdx.x * 128;

    const __half* Qg = g_Qh + (size_t)bh * SEQ * HDIM;
    const __half* Kg = g_Kh + (size_t)bh * SEQ * HDIM;
    const __half* Vg = g_Vh + (size_t)bh * SEQ * HDIM;

    uint32_t Qs_u = smem_u32(smh);
    uint32_t Ks_u = Qs_u + Q_TILE_H * 2;
    uint32_t Vs_u = Ks_u + 2 * KV_TILE_H * 2;

    auto issue_kv = [&](int kt, int st) {
        const int kbase = kt * 64;
        #pragma unroll
        for (int j = 0; j < 2; j++) {
            int i  = tid + j * 256;
            int r  = i >> 3;
            int c8 = (i & 7) << 3;
            int ki = kbase + r;
            bool p = ki < SEQ;
            uint32_t off = (uint32_t)(st * KV_TILE_H + r * LDH + c8) * 2;
            cp16(Ks_u + off, Kg + (size_t)ki * HDIM + c8, p);
            cp16(Vs_u + off, Vg + (size_t)ki * HDIM + c8, p);
        }
        CP_COMMIT();
    };

    #pragma unroll
    for (int j = 0; j < 4; j++) {
        int i  = tid + j * 256;
        int r  = i >> 3;
        int c8 = (i & 7) << 3;
        int qi = q0 + r;
        cp16(Qs_u + (uint32_t)(r * LDH + c8) * 2, Qg + (size_t)qi * HDIM + c8, qi < SEQ);
    }
    issue_kv(0, 0);

    CP_WAIT0();
    __syncthreads();

    uint32_t qa[4][4];
    {
        const int l8  = lane & 7;
        const int sel = lane >> 3;
        #pragma unroll
        for (int kk = 0; kk < 4; kk++) {
            uint32_t addr = Qs_u +
                (uint32_t)((warp * 16 + (sel & 1) * 8 + l8) * LDH + kk * 16 + (sel >> 1) * 8) * 2;
            ldsm_x4(qa[kk], addr);
        }
    }
    if (KV_TILES > 1) issue_kv(1, 1);

    float o[8][4];
    #pragma unroll
    for (int j = 0; j < 8; j++)
        #pragma unroll
        for (int c = 0; c < 4; c++) o[j][c] = 0.f;
    float mrow[2] = {-1e30f, -1e30f};
    float lrow[2] = {0.f, 0.f};

    const int l8  = lane & 7;
    const int grp = lane >> 3;       // 0..3

    for (int kt = 0; kt < KV_TILES; kt++) {
        const int st = kt & 1;
        if (kt > 0) {
            CP_WAIT0();
            __syncthreads();
            if (kt + 1 < KV_TILES) issue_kv(kt + 1, st ^ 1);
        }
        const uint32_t Kt_u = Ks_u + (uint32_t)(st * KV_TILE_H) * 2;
        const uint32_t Vt_u = Vs_u + (uint32_t)(st * KV_TILE_H) * 2;

        float s[8][4];
        #pragma unroll
        for (int j = 0; j < 8; j++)
            #pragma unroll
            for (int c = 0; c < 4; c++) s[j][c] = 0.f;

        #pragma unroll
        for (int kk = 0; kk < 4; kk++) {
            #pragma unroll
            for (int jp = 0; jp < 4; jp++) {
                uint32_t bk[4];
                uint32_t addr = Kt_u +
                    (uint32_t)(((jp * 2 + (grp >> 1)) * 8 + l8) * LDH
                               + kk * 16 + (grp & 1) * 8) * 2;
                ldsm_x4(bk, addr);
                mma16816(s[jp * 2 + 0], qa[kk], bk[0], bk[1]);
                mma16816(s[jp * 2 + 1], qa[kk], bk[2], bk[3]);
            }
        }

        const int kvc = kt * 64 + 2 * (lane & 3);
        float mx0 = mrow[0], mx1 = mrow[1];
        #pragma unroll
        for (int j = 0; j < 8; j++) {
            int kv = kvc + j * 8;
            if (kv     >= SEQ) { s[j][0] = -1e30f; s[j][2] = -1e30f; }
            if (kv + 1 >= SEQ) { s[j][1] = -1e30f; s[j][3] = -1e30f; }
            mx0 = fmaxf(mx0, fmaxf(s[j][0], s[j][1]));
            mx1 = fmaxf(mx1, fmaxf(s[j][2], s[j][3]));
        }
        mx0 = fmaxf(mx0, __shfl_xor_sync(0xffffffffu, mx0, 1));
        mx0 = fmaxf(mx0, __shfl_xor_sync(0xffffffffu, mx0, 2));
        mx1 = fmaxf(mx1, __shfl_xor_sync(0xffffffffu, mx1, 1));
        mx1 = fmaxf(mx1, __shfl_xor_sync(0xffffffffu, mx1, 2));

        const float alpha0 = ex2(mrow[0] - mx0);
        const float alpha1 = ex2(mrow[1] - mx1);
        mrow[0] = mx0; mrow[1] = mx1;

        float ls0 = 0.f, ls1 = 0.f;
        uint32_t pa[4][4];
        #pragma unroll
        for (int j = 0; j < 8; j++) {
            float p0 = ex2(s[j][0] - mx0);
            float p1 = ex2(s[j][1] - mx0);
            float p2 = ex2(s[j][2] - mx1);
            float p3 = ex2(s[j][3] - mx1);
            ls0 += p0 + p1;
            ls1 += p2 + p3;
            __half2 h01 = __floats2half2_rn(p0, p1);
            __half2 h23 = __floats2half2_rn(p2, p3);
            pa[j >> 1][(j & 1) * 2 + 0] = *(uint32_t*)&h01;
            pa[j >> 1][(j & 1) * 2 + 1] = *(uint32_t*)&h23;
        }
        ls0 += __shfl_xor_sync(0xffffffffu, ls0, 1);
        ls0 += __shfl_xor_sync(0xffffffffu, ls0, 2);
        ls1 += __shfl_xor_sync(0xffffffffu, ls1, 1);
        ls1 += __shfl_xor_sync(0xffffffffu, ls1, 2);
        lrow[0] = lrow[0] * alpha0 + ls0;
        lrow[1] = lrow[1] * alpha1 + ls1;

        #pragma unroll
        for (int j = 0; j < 8; j++) {
            o[j][0] *= alpha0; o[j][1] *= alpha0;
            o[j][2] *= alpha1; o[j][3] *= alpha1;
        }

        #pragma unroll
        for (int kk = 0; kk < 4; kk++) {
            #pragma unroll
            for (int jp = 0; jp < 4; jp++) {
                uint32_t bv[4];
                uint32_t addr = Vt_u +
                    (uint32_t)((kk * 16 + (grp & 1) * 8 + l8) * LDH
                               + (jp * 2 + (grp >> 1)) * 8) * 2;
                ldsm_x4t(bv, addr);
                mma16816(o[jp * 2 + 0], pa[kk], bv[0], bv[1]);
                mma16816(o[jp * 2 + 1], pa[kk], bv[2], bv[3]);
            }
        }
    }

    // ---- epilogue: stage normalized O into Qs smem (dead), then coalesced --
    const float rinv0 = 1.0f / lrow[0];
    const float rinv1 = 1.0f / lrow[1];
    {
        const int r0 = warp * 16 + (lane >> 2);
        const int c0 = 2 * (lane & 3);
        #pragma unroll
        for (int j = 0; j < 8; j++) {
            int c = c0 + j * 8;
            *(__half2*)(smh + r0 * LDH + c) =
                __floats2half2_rn(o[j][0] * rinv0, o[j][1] * rinv0);
            *(__half2*)(smh + (r0 + 8) * LDH + c) =
                __floats2half2_rn(o[j][2] * rinv1, o[j][3] * rinv1);
        }
    }
    __syncthreads();

    // coalesced O stores: 128 rows x 8 chunks of 16B (full sectors)
    const size_t obase = (size_t)(b * SEQ) * EMBED + h * HDIM;
    #pragma unroll
    for (int k = 0; k < 4; k++) {
        int idx = tid + k * 256;
        int r = idx >> 3;
        int c = idx & 7;
        int qi = q0 + r;
        if (qi >= SEQ) continue;
        *(uint4*)(g_Oh + obase + (size_t)qi * EMBED + c * 8) =
            *(const uint4*)(smh + r * LDH + c * 8);
    }
}

// ===========================================================================
// Aux: fused fp32->fp16 conversion (MLP-4, from R13)
// ===========================================================================
#define N8_X  ((size_t)MROWS * EMBED / 8)
#define N8_W1 ((size_t)EMBED * QKV_N / 8)
#define N8_W2 ((size_t)EMBED * EMBED / 8)
#define N8_TOT (N8_X + N8_W1 + N8_W2)

__device__ __forceinline__ void f2h_one(const float* __restrict__ src,
                                        __half* __restrict__ dst, size_t k)
{
    float4 a = ((const float4*)src)[2 * k];
    float4 b = ((const float4*)src)[2 * k + 1];
    __half2 h0 = __floats2half2_rn(a.x, a.y);
    __half2 h1 = __floats2half2_rn(a.z, a.w);
    __half2 h2 = __floats2half2_rn(b.x, b.y);
    __half2 h3 = __floats2half2_rn(b.z, b.w);
    uint4 o;
    o.x = *(uint32_t*)&h0; o.y = *(uint32_t*)&h1;
    o.z = *(uint32_t*)&h2; o.w = *(uint32_t*)&h3;
    ((uint4*)dst)[k] = o;
}

__device__ __forceinline__ void f2h_route(size_t i, const float* __restrict__ x,
                                          const float* __restrict__ w1,
                                          const float* __restrict__ w2,
                                          const float*& src, __half*& dst, size_t& k)
{
    if (i < N8_X)              { src = x;  dst = g_Xh;     k = i; }
    else if (i < N8_X + N8_W1) { src = w1; dst = g_Wqkvh;  k = i - N8_X; }
    else                       { src = w2; dst = g_Wprojh; k = i - N8_X - N8_W1; }
}

__global__ void __launch_bounds__(256) f2h_all_kernel(const float* __restrict__ x,
                                                      const float* __restrict__ w1,
                                                      const float* __restrict__ w2)
{
    const size_t stride = (size_t)gridDim.x * blockDim.x;
    size_t i = blockIdx.x * blockDim.x + threadIdx.x;

    for (; i + stride < N8_TOT; i += 2 * stride) {
        const float *s0, *s1;
        __half *d0, *d1;
        size_t k0, k1;
        f2h_route(i,          x, w1, w2, s0, d0, k0);
        f2h_route(i + stride, x, w1, w2, s1, d1, k1);
        float4 a0 = ((const float4*)s0)[2 * k0];
        float4 b0 = ((const float4*)s0)[2 * k0 + 1];
        float4 a1 = ((const float4*)s1)[2 * k1];
        float4 b1 = ((const float4*)s1)[2 * k1 + 1];
        {
            __half2 h0 = __floats2half2_rn(a0.x, a0.y);
            __half2 h1 = __floats2half2_rn(a0.z, a0.w);
            __half2 h2 = __floats2half2_rn(b0.x, b0.y);
            __half2 h3 = __floats2half2_rn(b0.z, b0.w);
            uint4 o;
            o.x = *(uint32_t*)&h0; o.y = *(uint32_t*)&h1;
            o.z = *(uint32_t*)&h2; o.w = *(uint32_t*)&h3;
            ((uint4*)d0)[k0] = o;
        }
        {
            __half2 h0 = __floats2half2_rn(a1.x, a1.y);
            __half2 h1 = __floats2half2_rn(a1.z, a1.w);
            __half2 h2 = __floats2half2_rn(b1.x, b1.y);
            __half2 h3 = __floats2half2_rn(b1.z, b1.w);
            uint4 o;
            o.x = *(uint32_t*)&h0; o.y = *(uint32_t*)&h1;
            o.z = *(uint32_t*)&h2; o.w = *(uint32_t*)&h3;
            ((uint4*)d1)[k1] = o;
        }
    }
    for (; i < N8_TOT; i += stride) {
        const float* s;
        __half* d;
        size_t k;
        f2h_route(i, x, w1, w2, s, d, k);
        f2h_one(s, d, k);
    }
}

// ===========================================================================
extern "C" void kernel_launch(void* const* d_in, const int* in_sizes, int n_in,
                              void* d_out, int out_size)
{
    (void)in_sizes; (void)n_in; (void)out_size;
    const float* x      = (const float*)d_in[0];
    const float* w_qkv  = (const float*)d_in[1];
    const float* w_proj = (const float*)d_in[2];
    const float* b_proj = (const float*)d_in[3];
    float* out = (float*)d_out;

    cudaFuncSetAttribute(gemm_qkv_kernel,  cudaFuncAttributeMaxDynamicSharedMemorySize, GEMM_SMEM_BYTES);
    cudaFuncSetAttribute(gemm_proj_kernel, cudaFuncAttributeMaxDynamicSharedMemorySize, GEMM_SMEM_BYTES);
    cudaFuncSetAttribute(attn_kernel,      cudaFuncAttributeMaxDynamicSharedMemorySize, (int)ATTN_SMEM);

    __half *dXh, *dWqkvh, *dWprojh, *dOh;
    cudaGetSymbolAddress((void**)&dXh,     g_Xh);
    cudaGetSymbolAddress((void**)&dWqkvh,  g_Wqkvh);
    cudaGetSymbolAddress((void**)&dWprojh, g_Wprojh);
    cudaGetSymbolAddress((void**)&dOh,     g_Oh);

    f2h_all_kernel<<<2048, 256>>>(x, w_qkv, w_proj);

    const int mblocks = (MROWS + BM - 1) / BM;   // 145
    gemm_qkv_kernel<<<dim3(QKV_N / BN, mblocks), 256, GEMM_SMEM_BYTES>>>(dXh, dWqkvh);

    const int qblocks = (SEQ + 127) / 128;       // 5
    attn_kernel<<<dim3(qblocks, BATCH * HEADS), 256, ATTN_SMEM>>>();

    gemm_proj_kernel<<<dim3(EMBED / BN, mblocks), 256, GEMM_SMEM_BYTES>>>(dOh, dWprojh, b_proj, out);
}

// round 15
// speedup vs baseline: 1.1282x; 1.0004x over previous
#include <cuda_runtime.h>
#include <cuda_fp16.h>
#include <cstdint>

#define BATCH   32
#define SEQ     577
#define EMBED   768
#define HEADS   12
#define HDIM    64
#define MROWS   (BATCH * SEQ)        // 18464
#define QKV_N   (3 * EMBED)          // 2304
// log2 domain: Q pre-scaled by ATT_SCALE * log2(e); softmax uses ex2.approx
#define ATT_SCALE_LOG2E 0.1803368801111204f

// ---------------- scratch (module-load allocated, no runtime allocs) -------
__device__ __half g_Qh[(size_t)BATCH * HEADS * SEQ * HDIM];   // [b,h,n,d], pre-scaled
__device__ __half g_Kh[(size_t)BATCH * HEADS * SEQ * HDIM];
__device__ __half g_Vh[(size_t)BATCH * HEADS * SEQ * HDIM];
__device__ __half g_Oh[(size_t)MROWS * EMBED];                // attention out (half)
__device__ __half g_Xh[(size_t)MROWS * EMBED];                // half X
__device__ __half g_Wqkvh[(size_t)EMBED * QKV_N];             // half W_qkv (row-major)
__device__ __half g_Wprojh[(size_t)EMBED * EMBED];            // half W_proj (row-major)

// ---------------- PTX helpers ----------------------------------------------
__device__ __forceinline__ uint32_t smem_u32(const void* p) {
    uint32_t a;
    asm("{ .reg .u64 t; cvta.to.shared.u64 t, %1; cvt.u32.u64 %0, t; }"
        : "=r"(a) : "l"(p));
    return a;
}
__device__ __forceinline__ void cp16(uint32_t dst, const void* src, bool pred) {
    int sz = pred ? 16 : 0;
    asm volatile("cp.async.cg.shared.global [%0], [%1], 16, %2;\n"
                 :: "r"(dst), "l"(src), "r"(sz));
}
#define CP_COMMIT() asm volatile("cp.async.commit_group;\n" ::: "memory")
#define CP_WAIT1()  asm volatile("cp.async.wait_group 1;\n" ::: "memory")
#define CP_WAIT0()  asm volatile("cp.async.wait_group 0;\n" ::: "memory")

__device__ __forceinline__ void ldsm_x4(uint32_t (&r)[4], uint32_t addr) {
    asm volatile("ldmatrix.sync.aligned.m8n8.x4.shared.b16 {%0,%1,%2,%3}, [%4];"
                 : "=r"(r[0]), "=r"(r[1]), "=r"(r[2]), "=r"(r[3]) : "r"(addr));
}
__device__ __forceinline__ void ldsm_x4t(uint32_t (&r)[4], uint32_t addr) {
    asm volatile("ldmatrix.sync.aligned.m8n8.x4.trans.shared.b16 {%0,%1,%2,%3}, [%4];"
                 : "=r"(r[0]), "=r"(r[1]), "=r"(r[2]), "=r"(r[3]) : "r"(addr));
}
__device__ __forceinline__ void mma16816(float (&d)[4], const uint32_t (&a)[4],
                                         uint32_t b0, uint32_t b1) {
    asm volatile("mma.sync.aligned.m16n8k16.row.col.f32.f16.f16.f32 "
                 "{%0,%1,%2,%3}, {%4,%5,%6,%7}, {%8,%9}, {%0,%1,%2,%3};"
                 : "+f"(d[0]), "+f"(d[1]), "+f"(d[2]), "+f"(d[3])
                 : "r"(a[0]), "r"(a[1]), "r"(a[2]), "r"(a[3]), "r"(b0), "r"(b1));
}
__device__ __forceinline__ float ex2(float x) {
    float r;
    asm("ex2.approx.ftz.f32 %0, %1;" : "=f"(r) : "f"(x));
    return r;
}

// ---------------- GEMM tiling (raw mma, fp16) -------------------------------
// BM=128, BN=128, BK=64; 8 warps as 2(m) x 4(n); warp tile 64x32.
// 3-stage cp.async pipeline + register-level B-fragment prefetch across kk.
#define BM 128
#define BN 128
#define BK 64
#define LDA 72
#define A_ST (BM * LDA)
#define B_ST_B 16384
#define KTILES (EMBED / BK)          // 12
#define GEMM_SMEM_BYTES (3 * (A_ST * 2 + B_ST_B))   // 104448

__device__ __forceinline__ void gemm_mma(
    const __half* __restrict__ Ag, const __half* __restrict__ Bg, int ldb_g,
    int m0, int n0, bool mtail, float (&acc)[4][4][4])
{
    extern __shared__ __half smh[];
    uint32_t sA_u = smem_u32(smh);
    uint32_t sB_u = sA_u + 3 * A_ST * 2;

    const int tid  = threadIdx.x;
    const int warp = tid >> 5;
    const int lane = tid & 31;
    const int wm   = warp >> 2;      // 0..1
    const int wn   = warp & 3;       // 0..3

    auto issue = [&](int kt, int st) {
        const int k0 = kt * BK;
        #pragma unroll
        for (int j = 0; j < 4; j++) {
            int i  = tid + j * 256;
            int r  = i >> 3;
            int ch = i & 7;
            int gm = m0 + r;
            bool p = !mtail || (gm < MROWS);
            cp16(sA_u + (uint32_t)(st * A_ST + r * LDA + ch * 8) * 2,
                 Ag + (size_t)gm * EMBED + k0 + ch * 8, p);
        }
        #pragma unroll
        for (int j = 0; j < 4; j++) {
            int i  = tid + j * 256;
            int r  = i >> 4;
            int c  = i & 15;
            cp16(sB_u + (uint32_t)(st * B_ST_B + r * 256 + ((c ^ (r & 7)) << 4)),
                 Bg + (size_t)(k0 + r) * ldb_g + n0 + c * 8, true);
        }
        CP_COMMIT();
    };

    #pragma unroll
    for (int i = 0; i < 4; i++)
        #pragma unroll
        for (int j = 0; j < 4; j++)
            #pragma unroll
            for (int c = 0; c < 4; c++) acc[i][j][c] = 0.f;

    issue(0, 0);
    issue(1, 1);

    const int l16 = lane & 15;
    const int lh  = lane >> 4;

    // B fragment smem offset for a given kk (within a stage)
    auto b_off = [&](int kk, int jj) -> uint32_t {
        int r = kk * 16 + l16;
        int c = wn * 4 + jj * 2 + lh;
        return (uint32_t)(r * 256 + ((c ^ (r & 7)) << 4));
    };

    for (int it = 0; it < KTILES; it++) {
        if (it == KTILES - 1) CP_WAIT0(); else CP_WAIT1();
        __syncthreads();

        const int st = it % 3;
        const uint32_t aBase = sA_u + (uint32_t)(st * A_ST) * 2;
        const uint32_t bBase = sB_u + (uint32_t)(st * B_ST_B);

        // preload B fragments for kk=0
        uint32_t bf[2][4];
        ldsm_x4t(bf[0], bBase + b_off(0, 0));
        ldsm_x4t(bf[1], bBase + b_off(0, 1));

        #pragma unroll
        for (int kk = 0; kk < 4; kk++) {
            // A fragments for this kk
            uint32_t am[4][4];
            #pragma unroll
            for (int i = 0; i < 4; i++) {
                int row = wm * 64 + i * 16 + l16;
                ldsm_x4(am[i], aBase + (uint32_t)(row * LDA + kk * 16 + lh * 8) * 2);
            }
            // prefetch next kk's B fragments (independent of this kk's MMAs)
            uint32_t bfn[2][4];
            if (kk < 3) {
                ldsm_x4t(bfn[0], bBase + b_off(kk + 1, 0));
                ldsm_x4t(bfn[1], bBase + b_off(kk + 1, 1));
            }
            // next tile's cp.async issue placed after kk=0 loads (keeps the
            // volatile block from fencing the fragment loads above it)
            if (kk == 0 && it + 2 < KTILES) issue(it + 2, (it + 2) % 3);

            #pragma unroll
            for (int i = 0; i < 4; i++) {
                #pragma unroll
                for (int jj = 0; jj < 2; jj++) {
                    mma16816(acc[i][jj * 2 + 0], am[i], bf[jj][0], bf[jj][1]);
                    mma16816(acc[i][jj * 2 + 1], am[i], bf[jj][2], bf[jj][3]);
                }
            }
            if (kk < 3) {
                #pragma unroll
                for (int jj = 0; jj < 2; jj++)
                    #pragma unroll
                    for (int c = 0; c < 4; c++) bf[jj][c] = bfn[jj][c];
            }
        }
    }
}

// ===========================================================================
// Kernel 1: QKV GEMM; epilogue stages C through smem (half, Q pre-scaled)
// then scatters in coalesced 16B chunks. n0 block lies in ONE q/k/v segment.
// ===========================================================================
#define LDC2 136   // smem halves per row for staged C tile

__global__ void __launch_bounds__(256, 2) gemm_qkv_kernel(const __half* __restrict__ X,
                                                          const __half* __restrict__ W)
{
    extern __shared__ __half smh[];
    const int m0 = blockIdx.y * BM;
    const int n0 = blockIdx.x * BN;
    const bool mtail = (m0 + BM > MROWS);

    float acc[4][4][4];
    gemm_mma(X, W, QKV_N, m0, n0, mtail, acc);

    __syncthreads();   // stages dead; reuse smem for C tile

    const int tid  = threadIdx.x;
    const int warp = tid >> 5;
    const int lane = tid & 31;
    const int wm   = warp >> 2;
    const int wn   = warp & 3;

    const int s   = n0 / EMBED;                 // entire block in one segment
    const float sc = (s == 0) ? ATT_SCALE_LOG2E : 1.0f;
    __half* base = (s == 0) ? g_Qh : (s == 1) ? g_Kh : g_Vh;
    const int rem0 = n0 - s * EMBED;

    // stage: acc -> smem half (conflict-free: row stride 272B)
    {
        const int r0 = wm * 64 + (lane >> 2);
        const int c0 = wn * 32 + 2 * (lane & 3);
        #pragma unroll
        for (int i = 0; i < 4; i++) {
            #pragma unroll
            for (int j = 0; j < 4; j++) {
                int c = c0 + j * 8;
                *(__half2*)(smh + (r0 + i * 16) * LDC2 + c) =
                    __floats2half2_rn(acc[i][j][0] * sc, acc[i][j][1] * sc);
                *(__half2*)(smh + (r0 + i * 16 + 8) * LDC2 + c) =
                    __floats2half2_rn(acc[i][j][2] * sc, acc[i][j][3] * sc);
            }
        }
    }
    __syncthreads();

    // coalesced scatter: 128 rows x 16 chunks of 16B
    #pragma unroll
    for (int k = 0; k < 8; k++) {
        int idx = tid + k * 256;
        int r = idx >> 4;
        int c = idx & 15;
        int gm = m0 + r;
        if (gm >= MROWS) continue;
        int rem = rem0 + c * 8;
        int h = rem >> 6;
        int d = rem & 63;
        int b = gm / SEQ;
        int tok = gm - b * SEQ;
        *(uint4*)(base + ((size_t)(b * HEADS + h) * SEQ + tok) * HDIM + d) =
            *(const uint4*)(smh + r * LDC2 + c * 8);
    }
}

// ===========================================================================
// Kernel 3: projection GEMM.  out = g_Oh @ Wp + bias  (float2 = full sectors)
// ===========================================================================
__global__ void __launch_bounds__(256, 2) gemm_proj_kernel(const __half* __restrict__ A,
                                                           const __half* __restrict__ W,
                                                           const float* __restrict__ bias,
                                                           float* __restrict__ out)
{
    const int m0 = blockIdx.y * BM;
    const int n0 = blockIdx.x * BN;
    const bool mtail = (m0 + BM > MROWS);

    float acc[4][4][4];
    gemm_mma(g_Oh + 0, W, EMBED, m0, n0, mtail, acc);
    (void)A;

    const int tid  = threadIdx.x;
    const int warp = tid >> 5;
    const int lane = tid & 31;
    const int wm   = warp >> 2;
    const int wn   = warp & 3;

    const int row0 = m0 + wm * 64 + (lane >> 2);
    const int gnb  = n0 + wn * 32 + 2 * (lane & 3);
    #pragma unroll
    for (int i = 0; i < 4; i++) {
        #pragma unroll
        for (int j = 0; j < 4; j++) {
            int gn = gnb + j * 8;
            int gm0 = row0 + i * 16;
            if (gm0 < MROWS) {
                float2 v;
                v.x = acc[i][j][0] + bias[gn];
                v.y = acc[i][j][1] + bias[gn + 1];
                *(float2*)(out + (size_t)gm0 * EMBED + gn) = v;
            }
            if (gm0 + 8 < MROWS) {
                float2 v;
                v.x = acc[i][j][2] + bias[gn];
                v.y = acc[i][j][3] + bias[gn + 1];
                *(float2*)(out + (size_t)(gm0 + 8) * EMBED + gn) = v;
            }
        }
    }
}

// ===========================================================================
// Kernel 2: flash attention (unchanged from R14 — staged coalesced epilogue)
// ===========================================================================
#define KV_TILES ((SEQ + 63) / 64)                 // 10
#define LDH 72
#define KV_TILE_H (64 * LDH)
#define Q_TILE_H  (128 * LDH)
#define ATTN_SMEM ((Q_TILE_H + 4 * KV_TILE_H) * 2) // 55296 B

__global__ void __launch_bounds__(256) attn_kernel()
{
    extern __shared__ __half smh[];
    const int tid  = threadIdx.x;
    const int warp = tid >> 5;
    const int lane = tid & 31;
    const int bh   = blockIdx.y;
    const int b    = bh / HEADS;
    const int h    = bh - b * HEADS;
    const int q0   = blockIdx.x * 128;

    const __half* Qg = g_Qh + (size_t)bh * SEQ * HDIM;
    const __half* Kg = g_Kh + (size_t)bh * SEQ * HDIM;
    const __half* Vg = g_Vh + (size_t)bh * SEQ * HDIM;

    uint32_t Qs_u = smem_u32(smh);
    uint32_t Ks_u = Qs_u + Q_TILE_H * 2;
    uint32_t Vs_u = Ks_u + 2 * KV_TILE_H * 2;

    auto issue_kv = [&](int kt, int st) {
        const int kbase = kt * 64;
        #pragma unroll
        for (int j = 0; j < 2; j++) {
            int i  = tid + j * 256;
            int r  = i >> 3;
            int c8 = (i & 7) << 3;
            int ki = kbase + r;
            bool p = ki < SEQ;
            uint32_t off = (uint32_t)(st * KV_TILE_H + r * LDH + c8) * 2;
            cp16(Ks_u + off, Kg + (size_t)ki * HDIM + c8, p);
            cp16(Vs_u + off, Vg + (size_t)ki * HDIM + c8, p);
        }
        CP_COMMIT();
    };

    #pragma unroll
    for (int j = 0; j < 4; j++) {
        int i  = tid + j * 256;
        int r  = i >> 3;
        int c8 = (i & 7) << 3;
        int qi = q0 + r;
        cp16(Qs_u + (uint32_t)(r * LDH + c8) * 2, Qg + (size_t)qi * HDIM + c8, qi < SEQ);
    }
    issue_kv(0, 0);

    CP_WAIT0();
    __syncthreads();

    uint32_t qa[4][4];
    {
        const int l8  = lane & 7;
        const int sel = lane >> 3;
        #pragma unroll
        for (int kk = 0; kk < 4; kk++) {
            uint32_t addr = Qs_u +
                (uint32_t)((warp * 16 + (sel & 1) * 8 + l8) * LDH + kk * 16 + (sel >> 1) * 8) * 2;
            ldsm_x4(qa[kk], addr);
        }
    }
    if (KV_TILES > 1) issue_kv(1, 1);

    float o[8][4];
    #pragma unroll
    for (int j = 0; j < 8; j++)
        #pragma unroll
        for (int c = 0; c < 4; c++) o[j][c] = 0.f;
    float mrow[2] = {-1e30f, -1e30f};
    float lrow[2] = {0.f, 0.f};

    const int l8  = lane & 7;
    const int grp = lane >> 3;       // 0..3

    for (int kt = 0; kt < KV_TILES; kt++) {
        const int st = kt & 1;
        if (kt > 0) {
            CP_WAIT0();
            __syncthreads();
            if (kt + 1 < KV_TILES) issue_kv(kt + 1, st ^ 1);
        }
        const uint32_t Kt_u = Ks_u + (uint32_t)(st * KV_TILE_H) * 2;
        const uint32_t Vt_u = Vs_u + (uint32_t)(st * KV_TILE_H) * 2;

        float s[8][4];
        #pragma unroll
        for (int j = 0; j < 8; j++)
            #pragma unroll
            for (int c = 0; c < 4; c++) s[j][c] = 0.f;

        #pragma unroll
        for (int kk = 0; kk < 4; kk++) {
            #pragma unroll
            for (int jp = 0; jp < 4; jp++) {
                uint32_t bk[4];
                uint32_t addr = Kt_u +
                    (uint32_t)(((jp * 2 + (grp >> 1)) * 8 + l8) * LDH
                               + kk * 16 + (grp & 1) * 8) * 2;
                ldsm_x4(bk, addr);
                mma16816(s[jp * 2 + 0], qa[kk], bk[0], bk[1]);
                mma16816(s[jp * 2 + 1], qa[kk], bk[2], bk[3]);
            }
        }

        const int kvc = kt * 64 + 2 * (lane & 3);
        float mx0 = mrow[0], mx1 = mrow[1];
        #pragma unroll
        for (int j = 0; j < 8; j++) {
            int kv = kvc + j * 8;
            if (kv     >= SEQ) { s[j][0] = -1e30f; s[j][2] = -1e30f; }
            if (kv + 1 >= SEQ) { s[j][1] = -1e30f; s[j][3] = -1e30f; }
            mx0 = fmaxf(mx0, fmaxf(s[j][0], s[j][1]));
            mx1 = fmaxf(mx1, fmaxf(s[j][2], s[j][3]));
        }
        mx0 = fmaxf(mx0, __shfl_xor_sync(0xffffffffu, mx0, 1));
        mx0 = fmaxf(mx0, __shfl_xor_sync(0xffffffffu, mx0, 2));
        mx1 = fmaxf(mx1, __shfl_xor_sync(0xffffffffu, mx1, 1));
        mx1 = fmaxf(mx1, __shfl_xor_sync(0xffffffffu, mx1, 2));

        const float alpha0 = ex2(mrow[0] - mx0);
        const float alpha1 = ex2(mrow[1] - mx1);
        mrow[0] = mx0; mrow[1] = mx1;

        float ls0 = 0.f, ls1 = 0.f;
        uint32_t pa[4][4];
        #pragma unroll
        for (int j = 0; j < 8; j++) {
            float p0 = ex2(s[j][0] - mx0);
            float p1 = ex2(s[j][1] - mx0);
            float p2 = ex2(s[j][2] - mx1);
            float p3 = ex2(s[j][3] - mx1);
            ls0 += p0 + p1;
            ls1 += p2 + p3;
            __half2 h01 = __floats2half2_rn(p0, p1);
            __half2 h23 = __floats2half2_rn(p2, p3);
            pa[j >> 1][(j & 1) * 2 + 0] = *(uint32_t*)&h01;
            pa[j >> 1][(j & 1) * 2 + 1] = *(uint32_t*)&h23;
        }
        ls0 += __shfl_xor_sync(0xffffffffu, ls0, 1);
        ls0 += __shfl_xor_sync(0xffffffffu, ls0, 2);
        ls1 += __shfl_xor_sync(0xffffffffu, ls1, 1);
        ls1 += __shfl_xor_sync(0xffffffffu, ls1, 2);
        lrow[0] = lrow[0] * alpha0 + ls0;
        lrow[1] = lrow[1] * alpha1 + ls1;

        #pragma unroll
        for (int j = 0; j < 8; j++) {
            o[j][0] *= alpha0; o[j][1] *= alpha0;
            o[j][2] *= alpha1; o[j][3] *= alpha1;
        }

        #pragma unroll
        for (int kk = 0; kk < 4; kk++) {
            #pragma unroll
            for (int jp = 0; jp < 4; jp++) {
                uint32_t bv[4];
                uint32_t addr = Vt_u +
                    (uint32_t)((kk * 16 + (grp & 1) * 8 + l8) * LDH
                               + (jp * 2 + (grp >> 1)) * 8) * 2;
                ldsm_x4t(bv, addr);
                mma16816(o[jp * 2 + 0], pa[kk], bv[0], bv[1]);
                mma16816(o[jp * 2 + 1], pa[kk], bv[2], bv[3]);
            }
        }
    }

    // epilogue: stage normalized O into Qs smem (dead), then coalesced stores
    const float rinv0 = 1.0f / lrow[0];
    const float rinv1 = 1.0f / lrow[1];
    {
        const int r0 = warp * 16 + (lane >> 2);
        const int c0 = 2 * (lane & 3);
        #pragma unroll
        for (int j = 0; j < 8; j++) {
            int c = c0 + j * 8;
            *(__half2*)(smh + r0 * LDH + c) =
                __floats2half2_rn(o[j][0] * rinv0, o[j][1] * rinv0);
            *(__half2*)(smh + (r0 + 8) * LDH + c) =
                __floats2half2_rn(o[j][2] * rinv1, o[j][3] * rinv1);
        }
    }
    __syncthreads();

    const size_t obase = (size_t)(b * SEQ) * EMBED + h * HDIM;
    #pragma unroll
    for (int k = 0; k < 4; k++) {
        int idx = tid + k * 256;
        int r = idx >> 3;
        int c = idx & 7;
        int qi = q0 + r;
        if (qi >= SEQ) continue;
        *(uint4*)(g_Oh + obase + (size_t)qi * EMBED + c * 8) =
            *(const uint4*)(smh + r * LDH + c * 8);
    }
}

// ===========================================================================
// Aux: fused fp32->fp16 conversion (MLP-4, from R13)
// ===========================================================================
#define N8_X  ((size_t)MROWS * EMBED / 8)
#define N8_W1 ((size_t)EMBED * QKV_N / 8)
#define N8_W2 ((size_t)EMBED * EMBED / 8)
#define N8_TOT (N8_X + N8_W1 + N8_W2)

__device__ __forceinline__ void f2h_one(const float* __restrict__ src,
                                        __half* __restrict__ dst, size_t k)
{
    float4 a = ((const float4*)src)[2 * k];
    float4 b = ((const float4*)src)[2 * k + 1];
    __half2 h0 = __floats2half2_rn(a.x, a.y);
    __half2 h1 = __floats2half2_rn(a.z, a.w);
    __half2 h2 = __floats2half2_rn(b.x, b.y);
    __half2 h3 = __floats2half2_rn(b.z, b.w);
    uint4 o;
    o.x = *(uint32_t*)&h0; o.y = *(uint32_t*)&h1;
    o.z = *(uint32_t*)&h2; o.w = *(uint32_t*)&h3;
    ((uint4*)dst)[k] = o;
}

__device__ __forceinline__ void f2h_route(size_t i, const float* __restrict__ x,
                                          const float* __restrict__ w1,
                                          const float* __restrict__ w2,
                                          const float*& src, __half*& dst, size_t& k)
{
    if (i < N8_X)              { src = x;  dst = g_Xh;     k = i; }
    else if (i < N8_X + N8_W1) { src = w1; dst = g_Wqkvh;  k = i - N8_X; }
    else                       { src = w2; dst = g_Wprojh; k = i - N8_X - N8_W1; }
}

__global__ void __launch_bounds__(256) f2h_all_kernel(const float* __restrict__ x,
                                                      const float* __restrict__ w1,
                                                      const float* __restrict__ w2)
{
    const size_t stride = (size_t)gridDim.x * blockDim.x;
    size_t i = blockIdx.x * blockDim.x + threadIdx.x;

    for (; i + stride < N8_TOT; i += 2 * stride) {
        const float *s0, *s1;
        __half *d0, *d1;
        size_t k0, k1;
        f2h_route(i,          x, w1, w2, s0, d0, k0);
        f2h_route(i + stride, x, w1, w2, s1, d1, k1);
        float4 a0 = ((const float4*)s0)[2 * k0];
        float4 b0 = ((const float4*)s0)[2 * k0 + 1];
        float4 a1 = ((const float4*)s1)[2 * k1];
        float4 b1 = ((const float4*)s1)[2 * k1 + 1];
        {
            __half2 h0 = __floats2half2_rn(a0.x, a0.y);
            __half2 h1 = __floats2half2_rn(a0.z, a0.w);
            __half2 h2 = __floats2half2_rn(b0.x, b0.y);
            __half2 h3 = __floats2half2_rn(b0.z, b0.w);
            uint4 o;
            o.x = *(uint32_t*)&h0; o.y = *(uint32_t*)&h1;
            o.z = *(uint32_t*)&h2; o.w = *(uint32_t*)&h3;
            ((uint4*)d0)[k0] = o;
        }
        {
            __half2 h0 = __floats2half2_rn(a1.x, a1.y);
            __half2 h1 = __floats2half2_rn(a1.z, a1.w);
            __half2 h2 = __floats2half2_rn(b1.x, b1.y);
            __half2 h3 = __floats2half2_rn(b1.z, b1.w);
            uint4 o;
            o.x = *(uint32_t*)&h0; o.y = *(uint32_t*)&h1;
            o.z = *(uint32_t*)&h2; o.w = *(uint32_t*)&h3;
            ((uint4*)d1)[k1] = o;
        }
    }
    for (; i < N8_TOT; i += stride) {
        const float* s;
        __half* d;
        size_t k;
        f2h_route(i, x, w1, w2, s, d, k);
        f2h_one(s, d, k);
    }
}

// ===========================================================================
extern "C" void kernel_launch(void* const* d_in, const int* in_sizes, int n_in,
                              void* d_out, int out_size)
{
    (void)in_sizes; (void)n_in; (void)out_size;
    const float* x      = (const float*)d_in[0];
    const float* w_qkv  = (const float*)d_in[1];
    const float* w_proj = (const float*)d_in[2];
    const float* b_proj = (const float*)d_in[3];
    float* out = (float*)d_out;

    cudaFuncSetAttribute(gemm_qkv_kernel,  cudaFuncAttributeMaxDynamicSharedMemorySize, GEMM_SMEM_BYTES);
    cudaFuncSetAttribute(gemm_proj_kernel, cudaFuncAttributeMaxDynamicSharedMemorySize, GEMM_SMEM_BYTES);
    cudaFuncSetAttribute(attn_kernel,      cudaFuncAttributeMaxDynamicSharedMemorySize, (int)ATTN_SMEM);

    __half *dXh, *dWqkvh, *dWprojh, *dOh;
    cudaGetSymbolAddress((void**)&dXh,     g_Xh);
    cudaGetSymbolAddress((void**)&dWqkvh,  g_Wqkvh);
    cudaGetSymbolAddress((void**)&dWprojh, g_Wprojh);
    cudaGetSymbolAddress((void**)&dOh,     g_Oh);

    f2h_all_kernel<<<2048, 256>>>(x, w_qkv, w_proj);

    const int mblocks = (MROWS + BM - 1) / BM;   // 145
    gemm_qkv_kernel<<<dim3(QKV_N / BN, mblocks), 256, GEMM_SMEM_BYTES>>>(dXh, dWqkvh);

    const int qblocks = (SEQ + 127) / 128;       // 5
    attn_kernel<<<dim3(qblocks, BATCH * HEADS), 256, ATTN_SMEM>>>();

    gemm_proj_kernel<<<dim3(EMBED / BN, mblocks), 256, GEMM_SMEM_BYTES>>>(dOh, dWprojh, b_proj, out);
}

// round 16
// speedup vs baseline: 1.1459x; 1.0157x over previous
#include <cuda_runtime.h>
#include <cuda_fp16.h>
#include <cstdint>

#define BATCH   32
#define SEQ     577
#define EMBED   768
#define HEADS   12
#define HDIM    64
#define MROWS   (BATCH * SEQ)        // 18464
#define QKV_N   (3 * EMBED)          // 2304
// log2 domain: Q pre-scaled by ATT_SCALE * log2(e); softmax uses ex2.approx
#define ATT_SCALE_LOG2E 0.1803368801111204f

// ---------------- scratch (module-load allocated, no runtime allocs) -------
__device__ __half g_Qh[(size_t)BATCH * HEADS * SEQ * HDIM];   // [b,h,n,d], pre-scaled
__device__ __half g_Kh[(size_t)BATCH * HEADS * SEQ * HDIM];
__device__ __half g_Vh[(size_t)BATCH * HEADS * SEQ * HDIM];
__device__ __half g_Oh[(size_t)MROWS * EMBED];                // attention out (half)
__device__ __half g_Xh[(size_t)MROWS * EMBED];                // half X
__device__ __half g_Wqkvh[(size_t)EMBED * QKV_N];             // half W_qkv (row-major)
__device__ __half g_Wprojh[(size_t)EMBED * EMBED];            // half W_proj (row-major)

// ---------------- PTX helpers ----------------------------------------------
__device__ __forceinline__ uint32_t smem_u32(const void* p) {
    uint32_t a;
    asm("{ .reg .u64 t; cvta.to.shared.u64 t, %1; cvt.u32.u64 %0, t; }"
        : "=r"(a) : "l"(p));
    return a;
}
__device__ __forceinline__ void cp16(uint32_t dst, const void* src, bool pred) {
    int sz = pred ? 16 : 0;
    asm volatile("cp.async.cg.shared.global [%0], [%1], 16, %2;\n"
                 :: "r"(dst), "l"(src), "r"(sz));
}
#define CP_COMMIT() asm volatile("cp.async.commit_group;\n" ::: "memory")
#define CP_WAIT1()  asm volatile("cp.async.wait_group 1;\n" ::: "memory")
#define CP_WAIT0()  asm volatile("cp.async.wait_group 0;\n" ::: "memory")

__device__ __forceinline__ void ldsm_x4(uint32_t (&r)[4], uint32_t addr) {
    asm volatile("ldmatrix.sync.aligned.m8n8.x4.shared.b16 {%0,%1,%2,%3}, [%4];"
                 : "=r"(r[0]), "=r"(r[1]), "=r"(r[2]), "=r"(r[3]) : "r"(addr));
}
__device__ __forceinline__ void ldsm_x4t(uint32_t (&r)[4], uint32_t addr) {
    asm volatile("ldmatrix.sync.aligned.m8n8.x4.trans.shared.b16 {%0,%1,%2,%3}, [%4];"
                 : "=r"(r[0]), "=r"(r[1]), "=r"(r[2]), "=r"(r[3]) : "r"(addr));
}
__device__ __forceinline__ void mma16816(float (&d)[4], const uint32_t (&a)[4],
                                         uint32_t b0, uint32_t b1) {
    asm volatile("mma.sync.aligned.m16n8k16.row.col.f32.f16.f16.f32 "
                 "{%0,%1,%2,%3}, {%4,%5,%6,%7}, {%8,%9}, {%0,%1,%2,%3};"
                 : "+f"(d[0]), "+f"(d[1]), "+f"(d[2]), "+f"(d[3])
                 : "r"(a[0]), "r"(a[1]), "r"(a[2]), "r"(a[3]), "r"(b0), "r"(b1));
}
__device__ __forceinline__ float ex2(float x) {
    float r;
    asm("ex2.approx.ftz.f32 %0, %1;" : "=f"(r) : "f"(x));
    return r;
}

// ---------------- GEMM tiling (raw mma, fp16) — R15 config ------------------
#define BM 128
#define BN 128
#define BK 64
#define LDA 72
#define A_ST (BM * LDA)
#define B_ST_B 16384
#define KTILES (EMBED / BK)          // 12
#define GEMM_SMEM_BYTES (3 * (A_ST * 2 + B_ST_B))   // 104448

__device__ __forceinline__ void gemm_mma(
    const __half* __restrict__ Ag, const __half* __restrict__ Bg, int ldb_g,
    int m0, int n0, bool mtail, float (&acc)[4][4][4])
{
    extern __shared__ __half smh[];
    uint32_t sA_u = smem_u32(smh);
    uint32_t sB_u = sA_u + 3 * A_ST * 2;

    const int tid  = threadIdx.x;
    const int warp = tid >> 5;
    const int lane = tid & 31;
    const int wm   = warp >> 2;      // 0..1
    const int wn   = warp & 3;       // 0..3

    auto issue = [&](int kt, int st) {
        const int k0 = kt * BK;
        #pragma unroll
        for (int j = 0; j < 4; j++) {
            int i  = tid + j * 256;
            int r  = i >> 3;
            int ch = i & 7;
            int gm = m0 + r;
            bool p = !mtail || (gm < MROWS);
            cp16(sA_u + (uint32_t)(st * A_ST + r * LDA + ch * 8) * 2,
                 Ag + (size_t)gm * EMBED + k0 + ch * 8, p);
        }
        #pragma unroll
        for (int j = 0; j < 4; j++) {
            int i  = tid + j * 256;
            int r  = i >> 4;
            int c  = i & 15;
            cp16(sB_u + (uint32_t)(st * B_ST_B + r * 256 + ((c ^ (r & 7)) << 4)),
                 Bg + (size_t)(k0 + r) * ldb_g + n0 + c * 8, true);
        }
        CP_COMMIT();
    };

    #pragma unroll
    for (int i = 0; i < 4; i++)
        #pragma unroll
        for (int j = 0; j < 4; j++)
            #pragma unroll
            for (int c = 0; c < 4; c++) acc[i][j][c] = 0.f;

    issue(0, 0);
    issue(1, 1);

    const int l16 = lane & 15;
    const int lh  = lane >> 4;

    auto b_off = [&](int kk, int jj) -> uint32_t {
        int r = kk * 16 + l16;
        int c = wn * 4 + jj * 2 + lh;
        return (uint32_t)(r * 256 + ((c ^ (r & 7)) << 4));
    };

    for (int it = 0; it < KTILES; it++) {
        if (it == KTILES - 1) CP_WAIT0(); else CP_WAIT1();
        __syncthreads();

        const int st = it % 3;
        const uint32_t aBase = sA_u + (uint32_t)(st * A_ST) * 2;
        const uint32_t bBase = sB_u + (uint32_t)(st * B_ST_B);

        uint32_t bf[2][4];
        ldsm_x4t(bf[0], bBase + b_off(0, 0));
        ldsm_x4t(bf[1], bBase + b_off(0, 1));

        #pragma unroll
        for (int kk = 0; kk < 4; kk++) {
            uint32_t am[4][4];
            #pragma unroll
            for (int i = 0; i < 4; i++) {
                int row = wm * 64 + i * 16 + l16;
                ldsm_x4(am[i], aBase + (uint32_t)(row * LDA + kk * 16 + lh * 8) * 2);
            }
            uint32_t bfn[2][4];
            if (kk < 3) {
                ldsm_x4t(bfn[0], bBase + b_off(kk + 1, 0));
                ldsm_x4t(bfn[1], bBase + b_off(kk + 1, 1));
            }
            if (kk == 0 && it + 2 < KTILES) issue(it + 2, (it + 2) % 3);

            #pragma unroll
            for (int i = 0; i < 4; i++) {
                #pragma unroll
                for (int jj = 0; jj < 2; jj++) {
                    mma16816(acc[i][jj * 2 + 0], am[i], bf[jj][0], bf[jj][1]);
                    mma16816(acc[i][jj * 2 + 1], am[i], bf[jj][2], bf[jj][3]);
                }
            }
            if (kk < 3) {
                #pragma unroll
                for (int jj = 0; jj < 2; jj++)
                    #pragma unroll
                    for (int c = 0; c < 4; c++) bf[jj][c] = bfn[jj][c];
            }
        }
    }
}

// ===========================================================================
// Kernel 1: QKV GEMM; staged smem epilogue, coalesced scatter (R14)
// ===========================================================================
#define LDC2 136

__global__ void __launch_bounds__(256, 2) gemm_qkv_kernel(const __half* __restrict__ X,
                                                          const __half* __restrict__ W)
{
    extern __shared__ __half smh[];
    const int m0 = blockIdx.y * BM;
    const int n0 = blockIdx.x * BN;
    const bool mtail = (m0 + BM > MROWS);

    float acc[4][4][4];
    gemm_mma(X, W, QKV_N, m0, n0, mtail, acc);

    __syncthreads();

    const int tid  = threadIdx.x;
    const int warp = tid >> 5;
    const int lane = tid & 31;
    const int wm   = warp >> 2;
    const int wn   = warp & 3;

    const int s   = n0 / EMBED;
    const float sc = (s == 0) ? ATT_SCALE_LOG2E : 1.0f;
    __half* base = (s == 0) ? g_Qh : (s == 1) ? g_Kh : g_Vh;
    const int rem0 = n0 - s * EMBED;

    {
        const int r0 = wm * 64 + (lane >> 2);
        const int c0 = wn * 32 + 2 * (lane & 3);
        #pragma unroll
        for (int i = 0; i < 4; i++) {
            #pragma unroll
            for (int j = 0; j < 4; j++) {
                int c = c0 + j * 8;
                *(__half2*)(smh + (r0 + i * 16) * LDC2 + c) =
                    __floats2half2_rn(acc[i][j][0] * sc, acc[i][j][1] * sc);
                *(__half2*)(smh + (r0 + i * 16 + 8) * LDC2 + c) =
                    __floats2half2_rn(acc[i][j][2] * sc, acc[i][j][3] * sc);
            }
        }
    }
    __syncthreads();

    #pragma unroll
    for (int k = 0; k < 8; k++) {
        int idx = tid + k * 256;
        int r = idx >> 4;
        int c = idx & 15;
        int gm = m0 + r;
        if (gm >= MROWS) continue;
        int rem = rem0 + c * 8;
        int h = rem >> 6;
        int d = rem & 63;
        int b = gm / SEQ;
        int tok = gm - b * SEQ;
        *(uint4*)(base + ((size_t)(b * HEADS + h) * SEQ + tok) * HDIM + d) =
            *(const uint4*)(smh + r * LDC2 + c * 8);
    }
}

// ===========================================================================
// Kernel 3: projection GEMM.  out = g_Oh @ Wp + bias
// ===========================================================================
__global__ void __launch_bounds__(256, 2) gemm_proj_kernel(const __half* __restrict__ A,
                                                           const __half* __restrict__ W,
                                                           const float* __restrict__ bias,
                                                           float* __restrict__ out)
{
    const int m0 = blockIdx.y * BM;
    const int n0 = blockIdx.x * BN;
    const bool mtail = (m0 + BM > MROWS);

    float acc[4][4][4];
    gemm_mma(g_Oh + 0, W, EMBED, m0, n0, mtail, acc);
    (void)A;

    const int tid  = threadIdx.x;
    const int warp = tid >> 5;
    const int lane = tid & 31;
    const int wm   = warp >> 2;
    const int wn   = warp & 3;

    const int row0 = m0 + wm * 64 + (lane >> 2);
    const int gnb  = n0 + wn * 32 + 2 * (lane & 3);
    #pragma unroll
    for (int i = 0; i < 4; i++) {
        #pragma unroll
        for (int j = 0; j < 4; j++) {
            int gn = gnb + j * 8;
            int gm0 = row0 + i * 16;
            if (gm0 < MROWS) {
                float2 v;
                v.x = acc[i][j][0] + bias[gn];
                v.y = acc[i][j][1] + bias[gn + 1];
                *(float2*)(out + (size_t)gm0 * EMBED + gn) = v;
            }
            if (gm0 + 8 < MROWS) {
                float2 v;
                v.x = acc[i][j][2] + bias[gn];
                v.y = acc[i][j][3] + bias[gn + 1];
                *(float2*)(out + (size_t)(gm0 + 8) * EMBED + gn) = v;
            }
        }
    }
}

// ===========================================================================
// Kernel 2: flash attention — 4 warps x 32 q-rows (halved K/V frag traffic).
// 128 threads; block = 128 q rows; KV tiles of 64, double buffered.
// ===========================================================================
#define ATHREADS 128
#define KV_TILES ((SEQ + 63) / 64)                 // 10
#define LDH 72
#define KV_TILE_H (64 * LDH)
#define Q_TILE_H  (128 * LDH)
#define ATTN_SMEM ((Q_TILE_H + 4 * KV_TILE_H) * 2) // 55296 B

__global__ void __launch_bounds__(ATHREADS) attn_kernel()
{
    extern __shared__ __half smh[];
    const int tid  = threadIdx.x;
    const int warp = tid >> 5;       // 0..3, covers q rows warp*32..+31
    const int lane = tid & 31;
    const int bh   = blockIdx.y;
    const int b    = bh / HEADS;
    const int h    = bh - b * HEADS;
    const int q0   = blockIdx.x * 128;

    const __half* Qg = g_Qh + (size_t)bh * SEQ * HDIM;
    const __half* Kg = g_Kh + (size_t)bh * SEQ * HDIM;
    const __half* Vg = g_Vh + (size_t)bh * SEQ * HDIM;

    uint32_t Qs_u = smem_u32(smh);
    uint32_t Ks_u = Qs_u + Q_TILE_H * 2;
    uint32_t Vs_u = Ks_u + 2 * KV_TILE_H * 2;

    auto issue_kv = [&](int kt, int st) {
        const int kbase = kt * 64;
        #pragma unroll
        for (int j = 0; j < 4; j++) {
            int i  = tid + j * ATHREADS;
            int r  = i >> 3;
            int c8 = (i & 7) << 3;
            int ki = kbase + r;
            bool p = ki < SEQ;
            uint32_t off = (uint32_t)(st * KV_TILE_H + r * LDH + c8) * 2;
            cp16(Ks_u + off, Kg + (size_t)ki * HDIM + c8, p);
            cp16(Vs_u + off, Vg + (size_t)ki * HDIM + c8, p);
        }
        CP_COMMIT();
    };

    #pragma unroll
    for (int j = 0; j < 8; j++) {
        int i  = tid + j * ATHREADS;
        int r  = i >> 3;
        int c8 = (i & 7) << 3;
        int qi = q0 + r;
        cp16(Qs_u + (uint32_t)(r * LDH + c8) * 2, Qg + (size_t)qi * HDIM + c8, qi < SEQ);
    }
    issue_kv(0, 0);

    CP_WAIT0();
    __syncthreads();

    // Q fragments: 2 m-tiles x 4 k-steps
    uint32_t qa[2][4][4];
    {
        const int l8  = lane & 7;
        const int sel = lane >> 3;
        #pragma unroll
        for (int i = 0; i < 2; i++) {
            #pragma unroll
            for (int kk = 0; kk < 4; kk++) {
                uint32_t addr = Qs_u +
                    (uint32_t)((warp * 32 + i * 16 + (sel & 1) * 8 + l8) * LDH
                               + kk * 16 + (sel >> 1) * 8) * 2;
                ldsm_x4(qa[i][kk], addr);
            }
        }
    }
    if (KV_TILES > 1) issue_kv(1, 1);

    float o[2][8][4];
    #pragma unroll
    for (int i = 0; i < 2; i++)
        #pragma unroll
        for (int j = 0; j < 8; j++)
            #pragma unroll
            for (int c = 0; c < 4; c++) o[i][j][c] = 0.f;
    float mrow[2][2] = {{-1e30f, -1e30f}, {-1e30f, -1e30f}};
    float lrow[2][2] = {{0.f, 0.f}, {0.f, 0.f}};

    const int l8  = lane & 7;
    const int grp = lane >> 3;       // 0..3

    for (int kt = 0; kt < KV_TILES; kt++) {
        const int st = kt & 1;
        if (kt > 0) {
            CP_WAIT0();
            __syncthreads();
            if (kt + 1 < KV_TILES) issue_kv(kt + 1, st ^ 1);
        }
        const uint32_t Kt_u = Ks_u + (uint32_t)(st * KV_TILE_H) * 2;
        const uint32_t Vt_u = Vs_u + (uint32_t)(st * KV_TILE_H) * 2;

        // ---- S = Q @ K^T : K frags shared across both m-tiles -------------
        float s[2][8][4];
        #pragma unroll
        for (int i = 0; i < 2; i++)
            #pragma unroll
            for (int j = 0; j < 8; j++)
                #pragma unroll
                for (int c = 0; c < 4; c++) s[i][j][c] = 0.f;

        #pragma unroll
        for (int kk = 0; kk < 4; kk++) {
            #pragma unroll
            for (int jp = 0; jp < 4; jp++) {
                uint32_t bk[4];
                uint32_t addr = Kt_u +
                    (uint32_t)(((jp * 2 + (grp >> 1)) * 8 + l8) * LDH
                               + kk * 16 + (grp & 1) * 8) * 2;
                ldsm_x4(bk, addr);
                #pragma unroll
                for (int i = 0; i < 2; i++) {
                    mma16816(s[i][jp * 2 + 0], qa[i][kk], bk[0], bk[1]);
                    mma16816(s[i][jp * 2 + 1], qa[i][kk], bk[2], bk[3]);
                }
            }
        }

        // ---- mask + online softmax per m-tile ------------------------------
        const int kvc = kt * 64 + 2 * (lane & 3);
        uint32_t pa[2][4][4];
        #pragma unroll
        for (int i = 0; i < 2; i++) {
            float mx0 = mrow[i][0], mx1 = mrow[i][1];
            #pragma unroll
            for (int j = 0; j < 8; j++) {
                int kv = kvc + j * 8;
                if (kv     >= SEQ) { s[i][j][0] = -1e30f; s[i][j][2] = -1e30f; }
                if (kv + 1 >= SEQ) { s[i][j][1] = -1e30f; s[i][j][3] = -1e30f; }
                mx0 = fmaxf(mx0, fmaxf(s[i][j][0], s[i][j][1]));
                mx1 = fmaxf(mx1, fmaxf(s[i][j][2], s[i][j][3]));
            }
            mx0 = fmaxf(mx0, __shfl_xor_sync(0xffffffffu, mx0, 1));
            mx0 = fmaxf(mx0, __shfl_xor_sync(0xffffffffu, mx0, 2));
            mx1 = fmaxf(mx1, __shfl_xor_sync(0xffffffffu, mx1, 1));
            mx1 = fmaxf(mx1, __shfl_xor_sync(0xffffffffu, mx1, 2));

            const float alpha0 = ex2(mrow[i][0] - mx0);
            const float alpha1 = ex2(mrow[i][1] - mx1);
            mrow[i][0] = mx0; mrow[i][1] = mx1;

            float ls0 = 0.f, ls1 = 0.f;
            #pragma unroll
            for (int j = 0; j < 8; j++) {
                float p0 = ex2(s[i][j][0] - mx0);
                float p1 = ex2(s[i][j][1] - mx0);
                float p2 = ex2(s[i][j][2] - mx1);
                float p3 = ex2(s[i][j][3] - mx1);
                ls0 += p0 + p1;
                ls1 += p2 + p3;
                __half2 h01 = __floats2half2_rn(p0, p1);
                __half2 h23 = __floats2half2_rn(p2, p3);
                pa[i][j >> 1][(j & 1) * 2 + 0] = *(uint32_t*)&h01;
                pa[i][j >> 1][(j & 1) * 2 + 1] = *(uint32_t*)&h23;
            }
            ls0 += __shfl_xor_sync(0xffffffffu, ls0, 1);
            ls0 += __shfl_xor_sync(0xffffffffu, ls0, 2);
            ls1 += __shfl_xor_sync(0xffffffffu, ls1, 1);
            ls1 += __shfl_xor_sync(0xffffffffu, ls1, 2);
            lrow[i][0] = lrow[i][0] * alpha0 + ls0;
            lrow[i][1] = lrow[i][1] * alpha1 + ls1;

            #pragma unroll
            for (int j = 0; j < 8; j++) {
                o[i][j][0] *= alpha0; o[i][j][1] *= alpha0;
                o[i][j][2] *= alpha1; o[i][j][3] *= alpha1;
            }
        }

        // ---- O += P @ V : V frags shared across both m-tiles ---------------
        #pragma unroll
        for (int kk = 0; kk < 4; kk++) {
            #pragma unroll
            for (int jp = 0; jp < 4; jp++) {
                uint32_t bv[4];
                uint32_t addr = Vt_u +
                    (uint32_t)((kk * 16 + (grp & 1) * 8 + l8) * LDH
                               + (jp * 2 + (grp >> 1)) * 8) * 2;
                ldsm_x4t(bv, addr);
                #pragma unroll
                for (int i = 0; i < 2; i++) {
                    mma16816(o[i][jp * 2 + 0], pa[i][kk], bv[0], bv[1]);
                    mma16816(o[i][jp * 2 + 1], pa[i][kk], bv[2], bv[3]);
                }
            }
        }
    }

    // ---- epilogue: stage normalized O into Qs smem, coalesced stores -------
    #pragma unroll
    for (int i = 0; i < 2; i++) {
        const float rinv0 = 1.0f / lrow[i][0];
        const float rinv1 = 1.0f / lrow[i][1];
        const int r0 = warp * 32 + i * 16 + (lane >> 2);
        const int c0 = 2 * (lane & 3);
        #pragma unroll
        for (int j = 0; j < 8; j++) {
            int c = c0 + j * 8;
            *(__half2*)(smh + r0 * LDH + c) =
                __floats2half2_rn(o[i][j][0] * rinv0, o[i][j][1] * rinv0);
            *(__half2*)(smh + (r0 + 8) * LDH + c) =
                __floats2half2_rn(o[i][j][2] * rinv1, o[i][j][3] * rinv1);
        }
    }
    __syncthreads();

    const size_t obase = (size_t)(b * SEQ) * EMBED + h * HDIM;
    #pragma unroll
    for (int k = 0; k < 8; k++) {
        int idx = tid + k * ATHREADS;
        int r = idx >> 3;
        int c = idx & 7;
        int qi = q0 + r;
        if (qi >= SEQ) continue;
        *(uint4*)(g_Oh + obase + (size_t)qi * EMBED + c * 8) =
            *(const uint4*)(smh + r * LDH + c * 8);
    }
}

// ===========================================================================
// Aux: fused fp32->fp16 conversion (MLP-4, from R13)
// ===========================================================================
#define N8_X  ((size_t)MROWS * EMBED / 8)
#define N8_W1 ((size_t)EMBED * QKV_N / 8)
#define N8_W2 ((size_t)EMBED * EMBED / 8)
#define N8_TOT (N8_X + N8_W1 + N8_W2)

__device__ __forceinline__ void f2h_one(const float* __restrict__ src,
                                        __half* __restrict__ dst, size_t k)
{
    float4 a = ((const float4*)src)[2 * k];
    float4 b = ((const float4*)src)[2 * k + 1];
    __half2 h0 = __floats2half2_rn(a.x, a.y);
    __half2 h1 = __floats2half2_rn(a.z, a.w);
    __half2 h2 = __floats2half2_rn(b.x, b.y);
    __half2 h3 = __floats2half2_rn(b.z, b.w);
    uint4 o;
    o.x = *(uint32_t*)&h0; o.y = *(uint32_t*)&h1;
    o.z = *(uint32_t*)&h2; o.w = *(uint32_t*)&h3;
    ((uint4*)dst)[k] = o;
}

__device__ __forceinline__ void f2h_route(size_t i, const float* __restrict__ x,
                                          const float* __restrict__ w1,
                                          const float* __restrict__ w2,
                                          const float*& src, __half*& dst, size_t& k)
{
    if (i < N8_X)              { src = x;  dst = g_Xh;     k = i; }
    else if (i < N8_X + N8_W1) { src = w1; dst = g_Wqkvh;  k = i - N8_X; }
    else                       { src = w2; dst = g_Wprojh; k = i - N8_X - N8_W1; }
}

__global__ void __launch_bounds__(256) f2h_all_kernel(const float* __restrict__ x,
                                                      const float* __restrict__ w1,
                                                      const float* __restrict__ w2)
{
    const size_t stride = (size_t)gridDim.x * blockDim.x;
    size_t i = blockIdx.x * blockDim.x + threadIdx.x;

    for (; i + stride < N8_TOT; i += 2 * stride) {
        const float *s0, *s1;
        __half *d0, *d1;
        size_t k0, k1;
        f2h_route(i,          x, w1, w2, s0, d0, k0);
        f2h_route(i + stride, x, w1, w2, s1, d1, k1);
        float4 a0 = ((const float4*)s0)[2 * k0];
        float4 b0 = ((const float4*)s0)[2 * k0 + 1];
        float4 a1 = ((const float4*)s1)[2 * k1];
        float4 b1 = ((const float4*)s1)[2 * k1 + 1];
        {
            __half2 h0 = __floats2half2_rn(a0.x, a0.y);
            __half2 h1 = __floats2half2_rn(a0.z, a0.w);
            __half2 h2 = __floats2half2_rn(b0.x, b0.y);
            __half2 h3 = __floats2half2_rn(b0.z, b0.w);
            uint4 o;
            o.x = *(uint32_t*)&h0; o.y = *(uint32_t*)&h1;
            o.z = *(uint32_t*)&h2; o.w = *(uint32_t*)&h3;
            ((uint4*)d0)[k0] = o;
        }
        {
            __half2 h0 = __floats2half2_rn(a1.x, a1.y);
            __half2 h1 = __floats2half2_rn(a1.z, a1.w);
            __half2 h2 = __floats2half2_rn(b1.x, b1.y);
            __half2 h3 = __floats2half2_rn(b1.z, b1.w);
            uint4 o;
            o.x = *(uint32_t*)&h0; o.y = *(uint32_t*)&h1;
            o.z = *(uint32_t*)&h2; o.w = *(uint32_t*)&h3;
            ((uint4*)d1)[k1] = o;
        }
    }
    for (; i < N8_TOT; i += stride) {
        const float* s;
        __half* d;
        size_t k;
        f2h_route(i, x, w1, w2, s, d, k);
        f2h_one(s, d, k);
    }
}

// ===========================================================================
extern "C" void kernel_launch(void* const* d_in, const int* in_sizes, int n_in,
                              void* d_out, int out_size)
{
    (void)in_sizes; (void)n_in; (void)out_size;
    const float* x      = (const float*)d_in[0];
    const float* w_qkv  = (const float*)d_in[1];
    const float* w_proj = (const float*)d_in[2];
    const float* b_proj = (const float*)d_in[3];
    float* out = (float*)d_out;

    cudaFuncSetAttribute(gemm_qkv_kernel,  cudaFuncAttributeMaxDynamicSharedMemorySize, GEMM_SMEM_BYTES);
    cudaFuncSetAttribute(gemm_proj_kernel, cudaFuncAttributeMaxDynamicSharedMemorySize, GEMM_SMEM_BYTES);
    cudaFuncSetAttribute(attn_kernel,      cudaFuncAttributeMaxDynamicSharedMemorySize, (int)ATTN_SMEM);

    __half *dXh, *dWqkvh, *dWprojh, *dOh;
    cudaGetSymbolAddress((void**)&dXh,     g_Xh);
    cudaGetSymbolAddress((void**)&dWqkvh,  g_Wqkvh);
    cudaGetSymbolAddress((void**)&dWprojh, g_Wprojh);
    cudaGetSymbolAddress((void**)&dOh,     g_Oh);

    f2h_all_kernel<<<2048, 256>>>(x, w_qkv, w_proj);

    const int mblocks = (MROWS + BM - 1) / BM;   // 145
    gemm_qkv_kernel<<<dim3(QKV_N / BN, mblocks), 256, GEMM_SMEM_BYTES>>>(dXh, dWqkvh);

    const int qblocks = (SEQ + 127) / 128;       // 5
    attn_kernel<<<dim3(qblocks, BATCH * HEADS), ATHREADS, ATTN_SMEM>>>();

    gemm_proj_kernel<<<dim3(EMBED / BN, mblocks), 256, GEMM_SMEM_BYTES>>>(dOh, dWprojh, b_proj, out);
}